// round 7
// baseline (speedup 1.0000x reference)
#include <cuda_runtime.h>
#include <cuda_bf16.h>
#include <cstdint>

// ---------------- problem constants ----------------
#define BATCH   2
#define NSEQ    1024
#define DIMF    512
#define HEADS   8
#define DKH     64
#define BH      16              // BATCH*HEADS
#define NN      1048576ull      // NSEQ*NSEQ
#define ND      65536ull        // NSEQ*DKH
#define NN16    16777216ull     // BH*NN

// ---------------- scratch pool (static device memory; allocation-free) -----
#define OFF_Q0  0ull
#define OFF_K0  1048576ull
#define OFF_V0  2097152ull
#define OFF_Q1  3145728ull
#define OFF_K1  4194304ull
#define OFF_V1  5242880ull
#define OFF_S0  6291456ull
#define OFF_S1  (OFF_S0 + NN16)
#define OFF_A0  (OFF_S1 + NN16)
#define OFF_A1  (OFF_A0 + NN16)
#define OFF_CF  (OFF_A1 + NN16)
#define OFF_CB  (OFF_CF + NN16)
#define OFF_TMP (OFF_CB + NN16)
#define OFF_YCH (OFF_TMP + 1048576ull)
#define OFF_YB  (OFF_YCH + 1048576ull)
#define OFF_Y   (OFF_YB  + 1048576ull)
#define OFF_SCR (OFF_Y   + 1048576ull)
#define POOL_TOTAL (OFF_SCR + 6291456ull)   // 117,440,512 floats = 470 MB

// fp8 pool (bytes): A0f, A1f row-major + transposes
#define OFF_F_A0  0ull
#define OFF_F_A1  NN16
#define OFF_F_A0T (2ull * NN16)
#define OFF_F_A1T (3ull * NN16)

static __device__ float   g_pool [POOL_TOTAL];
static __device__ uint8_t g_pool8[4ull * NN16];

// ---------------- helpers ----------------
__device__ __forceinline__ float tanh_fast(float x) {
    float y;
    asm("tanh.approx.f32 %0, %1;" : "=f"(y) : "f"(x));
    return y;
}

__device__ __forceinline__ uint32_t f2tf32(float x) {
    uint32_t u;
    asm("cvt.rna.tf32.f32 %0, %1;" : "=r"(u) : "f"(x));
    return u;
}

// pack 2 floats -> 2 e4m3 bytes (lo = a, hi = b)
__device__ __forceinline__ uint32_t f2e4m3x2(float a, float b) {
    uint16_t p;
    asm("cvt.rn.satfinite.e4m3x2.f32 %0, %1, %2;" : "=h"(p) : "f"(b), "f"(a));
    return (uint32_t)p;
}

__device__ __forceinline__ void mma_tf32(float* c, const uint32_t* a, const uint32_t* b) {
    asm volatile(
        "mma.sync.aligned.m16n8k8.row.col.f32.tf32.tf32.f32 "
        "{%0,%1,%2,%3}, {%4,%5,%6,%7}, {%8,%9}, {%0,%1,%2,%3};"
        : "+f"(c[0]), "+f"(c[1]), "+f"(c[2]), "+f"(c[3])
        : "r"(a[0]), "r"(a[1]), "r"(a[2]), "r"(a[3]), "r"(b[0]), "r"(b[1]));
}

__device__ __forceinline__ void mma_fp8(float* c, const uint32_t* a, const uint32_t* b) {
    asm volatile(
        "mma.sync.aligned.m16n8k32.row.col.f32.e4m3.e4m3.f32 "
        "{%0,%1,%2,%3}, {%4,%5,%6,%7}, {%8,%9}, {%0,%1,%2,%3};"
        : "+f"(c[0]), "+f"(c[1]), "+f"(c[2]), "+f"(c[3])
        : "r"(a[0]), "r"(a[1]), "r"(a[2]), "r"(a[3]), "r"(b[0]), "r"(b[1]));
}

__device__ __forceinline__ void cp16(void* smem_dst, const void* gmem_src) {
    uint32_t s = (uint32_t)__cvta_generic_to_shared(smem_dst);
    asm volatile("cp.async.cg.shared.global [%0], [%1], 16;\n" :: "r"(s), "l"(gmem_src));
}
__device__ __forceinline__ void cp_commit() {
    asm volatile("cp.async.commit_group;\n");
}
template<int N>
__device__ __forceinline__ void cp_wait() {
    asm volatile("cp.async.wait_group %0;\n" :: "n"(N));
}

__device__ __forceinline__ void ldsm_x4(uint32_t* r, const void* smem) {
    uint32_t a = (uint32_t)__cvta_generic_to_shared(smem);
    asm volatile("ldmatrix.sync.aligned.m8n8.x4.shared.b16 {%0,%1,%2,%3}, [%4];\n"
        : "=r"(r[0]), "=r"(r[1]), "=r"(r[2]), "=r"(r[3]) : "r"(a));
}

// =====================================================================
// tf32 tensor-core GEMM: C = alpha * A @ B (or A @ B^T), batched.
// DUAL=1: z<16 -> yb = A(Smix-softmax)@v0 ; z>=16 -> tmp = A1@v1
// =====================================================================
template<int BN, int WARPS_M, int WARPS_N, bool TRANSB, int DUAL>
__global__ __launch_bounds__(256) void gemm_tf32(
    const float* __restrict__ Aext, size_t offA,
    const float* __restrict__ Bext, size_t offB,
    float* __restrict__ Cext, size_t offC,
    int lda, int ldb, int ldc,
    long long sA, long long sB, long long sC,
    int K, float alpha)
{
    constexpr int BM = 128, BK = 32, LDS = BK + 4;     // stride 36
    constexpr int WM = BM / WARPS_M;
    constexpr int WN = BN / WARPS_N;
    constexpr int MT = WM / 16;
    constexpr int NT = WN / 8;
    constexpr int BITERS = BN / 32;

    const float* A;
    const float* B;
    float*       C;
    int z = blockIdx.z;
    if (DUAL) {
        if (z < 16) {
            A = g_pool + OFF_S0 + (size_t)z * NN;     // softmax(Smix)
            B = g_pool + OFF_V0 + (size_t)z * ND;
            C = g_pool + OFF_YB + (size_t)z * ND;
        } else {
            A = g_pool + OFF_A1 + (size_t)(z - 16) * NN;
            B = g_pool + OFF_V1 + (size_t)(z - 16) * ND;
            C = g_pool + OFF_TMP + (size_t)(z - 16) * ND;
        }
    } else {
        A = (Aext ? Aext : (g_pool + offA)) + (size_t)z * (size_t)sA;
        B = (Bext ? Bext : (g_pool + offB)) + (size_t)z * (size_t)sB;
        C = (Cext ? Cext : (g_pool + offC)) + (size_t)z * (size_t)sC;
    }

    __shared__ uint32_t As[BM][LDS];
    __shared__ uint32_t Bs[BN][LDS];   // stored [n][k]

    int tid  = threadIdx.x;
    int warp = tid >> 5, lane = tid & 31;
    int grp  = lane >> 2, kq = lane & 3;
    int bm = blockIdx.y * BM, bn = blockIdx.x * BN;
    int wm = (warp / WARPS_N) * WM, wn = (warp % WARPS_N) * WN;

    float acc[MT][NT][4] = {};

    for (int k0 = 0; k0 < K; k0 += BK) {
        #pragma unroll
        for (int i = 0; i < 4; i++) {
            int linear = i * 256 + tid;
            int r = linear >> 3, c4 = linear & 7;
            float4 v = *(const float4*)&A[(size_t)(bm + r) * lda + k0 + c4 * 4];
            uint4 u = make_uint4(f2tf32(v.x), f2tf32(v.y), f2tf32(v.z), f2tf32(v.w));
            *(uint4*)&As[r][c4 * 4] = u;
        }
        if (TRANSB) {
            #pragma unroll
            for (int i = 0; i < BITERS; i++) {
                int linear = i * 256 + tid;
                int n = linear >> 3, c4 = linear & 7;
                float4 v = *(const float4*)&B[(size_t)(bn + n) * ldb + k0 + c4 * 4];
                uint4 u = make_uint4(f2tf32(v.x), f2tf32(v.y), f2tf32(v.z), f2tf32(v.w));
                *(uint4*)&Bs[n][c4 * 4] = u;
            }
        } else {
            #pragma unroll
            for (int i = 0; i < BITERS; i++) {
                int linear = i * 256 + tid;
                int n4 = linear % (BN / 4), k = linear / (BN / 4);
                float4 v = *(const float4*)&B[(size_t)(k0 + k) * ldb + bn + n4 * 4];
                Bs[n4 * 4 + 0][k] = f2tf32(v.x);
                Bs[n4 * 4 + 1][k] = f2tf32(v.y);
                Bs[n4 * 4 + 2][k] = f2tf32(v.z);
                Bs[n4 * 4 + 3][k] = f2tf32(v.w);
            }
        }
        __syncthreads();

        #pragma unroll
        for (int ks = 0; ks < 4; ks++) {
            int kc = ks * 8 + kq;
            uint32_t a[MT][4], b[NT][2];
            #pragma unroll
            for (int mt = 0; mt < MT; mt++) {
                int r = wm + mt * 16 + grp;
                a[mt][0] = As[r][kc];
                a[mt][1] = As[r + 8][kc];
                a[mt][2] = As[r][kc + 4];
                a[mt][3] = As[r + 8][kc + 4];
            }
            #pragma unroll
            for (int nt = 0; nt < NT; nt++) {
                int n = wn + nt * 8 + grp;
                b[nt][0] = Bs[n][kc];
                b[nt][1] = Bs[n][kc + 4];
            }
            #pragma unroll
            for (int mt = 0; mt < MT; mt++)
                #pragma unroll
                for (int nt = 0; nt < NT; nt++)
                    mma_tf32(acc[mt][nt], a[mt], b[nt]);
        }
        __syncthreads();
    }

    #pragma unroll
    for (int mt = 0; mt < MT; mt++) {
        #pragma unroll
        for (int nt = 0; nt < NT; nt++) {
            int r = bm + wm + mt * 16 + grp;
            int c = bn + wn + nt * 8 + kq * 2;
            *(float2*)&C[(size_t)r * ldc + c] =
                make_float2(alpha * acc[mt][nt][0], alpha * acc[mt][nt][1]);
            *(float2*)&C[(size_t)(r + 8) * ldc + c] =
                make_float2(alpha * acc[mt][nt][2], alpha * acc[mt][nt][3]);
        }
    }
}

// =====================================================================
// Scatter x@Wqkv result into q/k/v [BH][N][DK] layouts
// =====================================================================
__global__ void scatter_qkv() {
    int idx = blockIdx.x * 256 + threadIdx.x;   // 0 .. 2*2048*1536-1
    if (idx >= 2 * 2048 * 1536) return;
    int w   = idx / (2048 * 1536);
    int rem = idx - w * (2048 * 1536);
    int m = rem / 1536;
    int j = rem - m * 1536;
    int b = m >> 10, tok = m & 1023;
    int s = j >> 9;
    int h = (j >> 6) & 7;
    int d = j & 63;
    float val = g_pool[OFF_SCR + (size_t)idx];
    size_t baseoff;
    if (w == 0) baseoff = (s == 0) ? OFF_Q0 : (s == 1) ? OFF_K0 : OFF_V0;
    else        baseoff = (s == 0) ? OFF_Q1 : (s == 1) ? OFF_K1 : OFF_V1;
    g_pool[baseoff + ((size_t)(b * 8 + h) * NSEQ + tok) * DKH + d] = val;
}

// =====================================================================
// Row softmax over 1024 elems (vectorized, 4 consecutive per thread).
// WB=1: also write fp8 copy of (p * 256) to g_pool8 + f8Off.
// =====================================================================
template<int WB>
__global__ __launch_bounds__(256) void softmax_rows(size_t inOff, size_t outOff, size_t f8Off)
{
    const float* S = g_pool + inOff;
    float*       A = g_pool + outOff;
    size_t base = (size_t)blockIdx.x * 1024;
    int tid = threadIdx.x;
    int warp = tid >> 5, lane = tid & 31;

    float4 v4 = *(const float4*)&S[base + tid * 4];
    float v[4] = { v4.x, v4.y, v4.z, v4.w };
    float mx = fmaxf(fmaxf(v[0], v[1]), fmaxf(v[2], v[3]));
    #pragma unroll
    for (int o = 16; o > 0; o >>= 1) mx = fmaxf(mx, __shfl_xor_sync(0xffffffffu, mx, o));
    __shared__ float red[8];
    if (lane == 0) red[warp] = mx;
    __syncthreads();
    float mAll = red[0];
    #pragma unroll
    for (int w = 1; w < 8; w++) mAll = fmaxf(mAll, red[w]);
    __syncthreads();

    float e[4], s = 0.f;
    #pragma unroll
    for (int i = 0; i < 4; i++) { e[i] = __expf(v[i] - mAll); s += e[i]; }
    #pragma unroll
    for (int o = 16; o > 0; o >>= 1) s += __shfl_xor_sync(0xffffffffu, s, o);
    if (lane == 0) red[warp] = s;
    __syncthreads();
    float tot = 0.f;
    #pragma unroll
    for (int w = 0; w < 8; w++) tot += red[w];
    float inv = __fdividef(1.0f, tot);

    float p[4];
    #pragma unroll
    for (int i = 0; i < 4; i++) p[i] = e[i] * inv;
    *(float4*)&A[base + tid * 4] = make_float4(p[0], p[1], p[2], p[3]);
    if (WB) {
        // scale by 256 (exact pow2) so near-uniform probs are e4m3-normal
        uint32_t lo = f2e4m3x2(p[0] * 256.0f, p[1] * 256.0f);
        uint32_t hi = f2e4m3x2(p[2] * 256.0f, p[3] * 256.0f);
        *(uint32_t*)&g_pool8[f8Off + base + tid * 4] = lo | (hi << 16);
    }
}

// =====================================================================
// fp8 transpose: A0fT[z] = A0f[z]^T, A1fT[z] = A1f[z]^T.
// grid (16, 16, 32): 64x64 byte tiles, 256 threads.
// =====================================================================
__global__ __launch_bounds__(256) void transpose_fp8() {
    __shared__ uint8_t t[64][68];
    int z = blockIdx.z;
    const uint8_t* S;
    uint8_t* D;
    if (z < 16) {
        S = g_pool8 + OFF_F_A0  + (size_t)z * NN;
        D = g_pool8 + OFF_F_A0T + (size_t)z * NN;
    } else {
        S = g_pool8 + OFF_F_A1  + (size_t)(z - 16) * NN;
        D = g_pool8 + OFF_F_A1T + (size_t)(z - 16) * NN;
    }
    int r0 = blockIdx.y * 64, c0 = blockIdx.x * 64;
    int tid = threadIdx.x;
    #pragma unroll
    for (int i = 0; i < 4; i++) {
        int idx = i * 256 + tid;
        int r = idx >> 4, c4 = idx & 15;
        *(uchar4*)&t[r][c4 * 4] = *(const uchar4*)&S[(size_t)(r0 + r) * 1024 + c0 + c4 * 4];
    }
    __syncthreads();
    #pragma unroll
    for (int i = 0; i < 4; i++) {
        int idx = i * 256 + tid;
        int orow = idx >> 4, oc4 = idx & 15;
        uchar4 o;
        o.x = t[oc4 * 4 + 0][orow];
        o.y = t[oc4 * 4 + 1][orow];
        o.z = t[oc4 * 4 + 2][orow];
        o.w = t[oc4 * 4 + 3][orow];
        *(uchar4*)&D[(size_t)(c0 + orow) * 1024 + r0 + oc4 * 4] = o;
    }
}

// =====================================================================
// Chain GEMM v4: FP8 e4m3 mma.sync m16n8k32, 3-stage cp.async, BK=128B.
// z<16: Cf[z] = A0[z] @ A1[z]  (A = A0f row-major, B rows = A1T rows)
// z>=16: Cb[z-16] = A1 @ A0    (A = A1f, B = A0T)
// CTA 128x128, 8 warps (2x4), warp tile 64x32. Inputs pre-scaled by 256;
// epilogue multiplies by 2^-16.
// =====================================================================
#define F8_STR   144
#define F8_AB    (128 * F8_STR)      // 18432 B per operand tile
#define F8_STAGE (2 * F8_AB)         // 36864 B
#define F8_SMEM  (3 * F8_STAGE)      // 110592 B

__global__ __launch_bounds__(256) void gemm_chain_fp8() {
    extern __shared__ uint8_t sm8[];

    int z = blockIdx.z;
    const uint8_t *A, *B;
    float* C;
    if (z < 16) {
        A = g_pool8 + OFF_F_A0  + (size_t)z * NN;
        B = g_pool8 + OFF_F_A1T + (size_t)z * NN;
        C = g_pool  + OFF_CF    + (size_t)z * NN;
    } else {
        int zz = z - 16;
        A = g_pool8 + OFF_F_A1  + (size_t)zz * NN;
        B = g_pool8 + OFF_F_A0T + (size_t)zz * NN;
        C = g_pool  + OFF_CB    + (size_t)zz * NN;
    }

    int tid = threadIdx.x, warp = tid >> 5, lane = tid & 31;
    int bm = blockIdx.y * 128, bn = blockIdx.x * 128;
    int wm = (warp >> 2) * 64, wn = (warp & 3) * 32;

    auto load_stage = [&](int chunk, int s) {
        uint8_t* Ab = sm8 + s * F8_STAGE;
        uint8_t* Bb = Ab + F8_AB;
        int k0 = chunk * 128;
        #pragma unroll
        for (int i = 0; i < 4; i++) {
            int idx = i * 256 + tid;
            int r = idx >> 3, c16 = idx & 7;
            cp16(Ab + r * F8_STR + c16 * 16, A + (size_t)(bm + r) * 1024 + k0 + c16 * 16);
        }
        #pragma unroll
        for (int i = 0; i < 4; i++) {
            int idx = i * 256 + tid;
            int r = idx >> 3, c16 = idx & 7;
            cp16(Bb + r * F8_STR + c16 * 16, B + (size_t)(bn + r) * 1024 + k0 + c16 * 16);
        }
    };

    float acc[4][4][4] = {};

    load_stage(0, 0); cp_commit();
    load_stage(1, 1); cp_commit();

    for (int c = 0; c < 8; c++) {
        cp_wait<1>();
        __syncthreads();

        if (c + 2 < 8) load_stage(c + 2, (c + 2) % 3);
        cp_commit();

        const uint8_t* Ab = sm8 + (c % 3) * F8_STAGE;
        const uint8_t* Bb = Ab + F8_AB;

        #pragma unroll
        for (int ks = 0; ks < 4; ks++) {
            int kb = ks * 32;
            uint32_t a[4][4], b[4][2];
            // A frags: 16 rows x 32 k-bytes per mt tile
            #pragma unroll
            for (int mt = 0; mt < 4; mt++)
                ldsm_x4(a[mt], Ab + (size_t)(wm + mt * 16 + (lane & 15)) * F8_STR
                                  + kb + ((lane >> 4) << 4));
            // B frags: rows = n, 32 k-bytes; one x4 covers two n-tiles of 8
            #pragma unroll
            for (int p = 0; p < 2; p++) {
                uint32_t r[4];
                ldsm_x4(r, Bb + (size_t)(wn + p * 16 + ((lane >> 4) << 3) + (lane & 7)) * F8_STR
                              + kb + (((lane >> 3) & 1) << 4));
                b[2 * p][0] = r[0];     b[2 * p][1] = r[1];
                b[2 * p + 1][0] = r[2]; b[2 * p + 1][1] = r[3];
            }
            #pragma unroll
            for (int mt = 0; mt < 4; mt++)
                #pragma unroll
                for (int nt = 0; nt < 4; nt++)
                    mma_fp8(acc[mt][nt], a[mt], b[nt]);
        }
    }

    const float sc = 1.0f / 65536.0f;   // undo 256*256 input scaling
    #pragma unroll
    for (int mt = 0; mt < 4; mt++) {
        #pragma unroll
        for (int nt = 0; nt < 4; nt++) {
            int r = bm + wm + mt * 16 + (lane >> 2);
            int cc = bn + wn + nt * 8 + (lane & 3) * 2;
            *(float2*)&C[(size_t)r * 1024 + cc] =
                make_float2(sc * acc[mt][nt][0], sc * acc[mt][nt][1]);
            *(float2*)&C[(size_t)(r + 8) * 1024 + cc] =
                make_float2(sc * acc[mt][nt][2], sc * acc[mt][nt][3]);
        }
    }
}

// =====================================================================
// Fused: feat -> conv1+gelu -> conv2+sigmoid -> gates -> Smix (in Cb).
// =====================================================================
__global__ __launch_bounds__(256) void fuse_kernel(
    const float* __restrict__ w1, const float* __restrict__ b1,
    const float* __restrict__ w2, const float* __restrict__ b2)
{
    __shared__ float s0t[32][33], s1t[32][33];
    __shared__ float w1s[16][6], b1s[16], w2s[4][16], b2s[4];

    size_t off = (size_t)blockIdx.z * NN;
    int m0 = blockIdx.y * 32, n0 = blockIdx.x * 32;
    int tid = threadIdx.x;
    int tx = tid & 31, ty = tid >> 5;

    if (tid < 96)       ((float*)w1s)[tid]        = w1[tid];
    else if (tid < 112) b1s[tid - 96]             = b1[tid - 96];
    else if (tid < 176) ((float*)w2s)[tid - 112]  = w2[tid - 112];
    else if (tid < 180) b2s[tid - 176]            = b2[tid - 176];

    const float* S0 = g_pool + OFF_S0;
    const float* S1 = g_pool + OFF_S1;
    const float* Cf = g_pool + OFF_CF;
    float*       Cb = g_pool + OFF_CB;

    #pragma unroll
    for (int r = 0; r < 4; r++) {
        int rr = ty + r * 8;
        s0t[rr][tx] = S0[off + (size_t)(n0 + rr) * 1024 + m0 + tx];
        s1t[rr][tx] = S1[off + (size_t)(n0 + rr) * 1024 + m0 + tx];
    }
    __syncthreads();

    #pragma unroll
    for (int r = 0; r < 4; r++) {
        int row = ty + r * 8;
        size_t gidx = off + (size_t)(m0 + row) * 1024 + n0 + tx;
        float s0 = S0[gidx], s1 = S1[gidx];
        float f2 = s0t[tx][row];   // S0^T
        float f3 = s1t[tx][row];   // S1^T
        float cr = __logf(Cf[gidx] + 1e-6f);
        float cl = __logf(Cb[gidx] + 1e-6f);
        float f[6] = { s0, s1, f2, f3, cr, cl };

        float g[4];
        #pragma unroll
        for (int o = 0; o < 4; o++) g[o] = b2s[o];

        #pragma unroll
        for (int oh = 0; oh < 16; oh++) {
            float a = b1s[oh];
            #pragma unroll
            for (int c = 0; c < 6; c++) a += w1s[oh][c] * f[c];
            float gx = 0.7978845608028654f * (a + 0.044715f * a * a * a);
            float hg = 0.5f * a * (1.0f + tanh_fast(gx));
            #pragma unroll
            for (int o = 0; o < 4; o++) g[o] += w2s[o][oh] * hg;
        }
        #pragma unroll
        for (int o = 0; o < 4; o++) g[o] = __fdividef(1.0f, 1.0f + __expf(-g[o]));

        float d   = fabsf(s0 - s1);
        float lse = fmaxf(s0, s1) + __logf(1.0f + __expf(-d));
        float smix = s0 + g[0] * s1 + g[1] * (lse - s0) - g[2] * (0.5f * s1) + g[3] * cr;
        Cb[gidx] = smix;
    }
}

// =====================================================================
// Combine: Y[b][tok][h*64+d] = yb + sigmoid(cvl) * ych
// =====================================================================
__global__ void combine_kernel(const float* __restrict__ cvl) {
    int idx = blockIdx.x * 256 + threadIdx.x;
    if (idx >= (int)(BH * ND)) return;
    int bh  = idx >> 16;
    int rr  = idx & 65535;
    int tok = rr >> 6;
    int d   = rr & 63;
    int b = bh >> 3, h = bh & 7;
    float sig = __fdividef(1.0f, 1.0f + __expf(-cvl[0]));
    float y = g_pool[OFF_YB + (size_t)idx] + sig * g_pool[OFF_YCH + (size_t)idx];
    g_pool[OFF_Y + ((size_t)(b * 1024 + tok)) * 512 + h * 64 + d] = y;
}

// =====================================================================
// Host launch sequence
// =====================================================================
extern "C" void kernel_launch(void* const* d_in, const int* in_sizes, int n_in,
                              void* d_out, int out_size)
{
    const float* x     = (const float*)d_in[0];
    const float* Wqkv0 = (const float*)d_in[1];
    const float* Wqkv1 = (const float*)d_in[2];
    const float* Wproj = (const float*)d_in[3];
    const float* c1w   = (const float*)d_in[4];
    const float* c1b   = (const float*)d_in[5];
    const float* c2w   = (const float*)d_in[6];
    const float* c2b   = (const float*)d_in[7];
    const float* cvl   = (const float*)d_in[8];
    float* out = (float*)d_out;

    cudaFuncSetAttribute(gemm_chain_fp8,
                         cudaFuncAttributeMaxDynamicSharedMemorySize, F8_SMEM);

    // 1) qkv GEMMs (tf32 TC)
    gemm_tf32<128, 2, 4, false, 0><<<dim3(12, 16, 1), 256>>>(x, 0, Wqkv0, 0, nullptr, OFF_SCR,
        512, 1536, 1536, 0, 0, 0, 512, 1.0f);
    gemm_tf32<128, 2, 4, false, 0><<<dim3(12, 16, 1), 256>>>(x, 0, Wqkv1, 0, nullptr, OFF_SCR + 3145728ull,
        512, 1536, 1536, 0, 0, 0, 512, 1.0f);

    // 2) scatter into q/k/v [BH][N][DK]
    scatter_qkv<<<(2 * 2048 * 1536 + 255) / 256, 256>>>();

    // 3) S0, S1 (batched NT, tf32 TC)
    gemm_tf32<128, 2, 4, true, 0><<<dim3(8, 8, 16), 256>>>(nullptr, OFF_Q0, nullptr, OFF_K0, nullptr, OFF_S0,
        64, 64, 1024, (long long)ND, (long long)ND, (long long)NN, 64, 0.125f);
    gemm_tf32<128, 2, 4, true, 0><<<dim3(8, 8, 16), 256>>>(nullptr, OFF_Q1, nullptr, OFF_K1, nullptr, OFF_S1,
        64, 64, 1024, (long long)ND, (long long)ND, (long long)NN, 64, 0.125f);

    // 4) softmaxes (+fp8 scaled copies)
    softmax_rows<1><<<16384, 256>>>(OFF_S0, OFF_A0, OFF_F_A0);
    softmax_rows<1><<<16384, 256>>>(OFF_S1, OFF_A1, OFF_F_A1);

    // 5) fp8 transposes (B operands for the chain GEMM)
    transpose_fp8<<<dim3(16, 16, 32), 256>>>();

    // 6) C_fwd / C_bwd (fp8 mma, 3-stage cp.async pipeline)
    gemm_chain_fp8<<<dim3(8, 8, 32), 256, F8_SMEM>>>();

    // 7) fused feat/conv/gates/Smix
    fuse_kernel<<<dim3(32, 32, 16), 256>>>(c1w, c1b, c2w, c2b);

    // 8) A = softmax(Smix) -> S0 buffer
    softmax_rows<0><<<16384, 256>>>(OFF_CB, OFF_S0, 0);

    // 9) yb = A @ v0 and tmp = A1 @ v1 in ONE launch (z=32, independent)
    gemm_tf32<64, 4, 2, false, 1><<<dim3(1, 8, 32), 256>>>(nullptr, 0, nullptr, 0, nullptr, 0,
        1024, 64, 64, 0, 0, 0, 1024, 1.0f);

    // 10) ych = A0 @ tmp
    gemm_tf32<64, 4, 2, false, 0><<<dim3(1, 8, 16), 256>>>(nullptr, OFF_A0, nullptr, OFF_TMP, nullptr, OFF_YCH,
        1024, 64, 64, (long long)NN, (long long)ND, (long long)ND, 1024, 1.0f);

    // 11) combine into Y
    combine_kernel<<<(BH * ND + 255) / 256, 256>>>(cvl);

    // 12) out = Y @ Wproj (tf32 TC)
    gemm_tf32<128, 2, 4, false, 0><<<dim3(4, 16, 1), 256>>>(nullptr, OFF_Y, Wproj, 0, out, 0,
        512, 512, 512, 0, 0, 0, 512, 1.0f);

    (void)in_sizes; (void)n_in; (void)out_size;
}

// round 9
// speedup vs baseline: 1.0939x; 1.0939x over previous
#include <cuda_runtime.h>
#include <cuda_bf16.h>
#include <cstdint>

// ---------------- problem constants ----------------
#define BATCH   2
#define NSEQ    1024
#define DIMF    512
#define HEADS   8
#define DKH     64
#define BH      16              // BATCH*HEADS
#define NN      1048576ull      // NSEQ*NSEQ
#define ND      65536ull        // NSEQ*DKH
#define NN16    16777216ull     // BH*NN

// ---------------- scratch pool (static device memory; allocation-free) -----
#define OFF_Q0  0ull
#define OFF_K0  1048576ull
#define OFF_V0  2097152ull
#define OFF_Q1  3145728ull
#define OFF_K1  4194304ull
#define OFF_V1  5242880ull
#define OFF_S0  6291456ull
#define OFF_S1  (OFF_S0 + NN16)
#define OFF_A0  (OFF_S1 + NN16)
#define OFF_A1  (OFF_A0 + NN16)
#define OFF_CF  (OFF_A1 + NN16)
#define OFF_CB  (OFF_CF + NN16)
#define OFF_TMP (OFF_CB + NN16)
#define OFF_YCH (OFF_TMP + 1048576ull)
#define OFF_YB  (OFF_YCH + 1048576ull)
#define OFF_Y   (OFF_YB  + 1048576ull)
#define POOL_TOTAL (OFF_Y + 1048576ull)

#define OFF_A0H 0ull
#define OFF_A1H NN16

static __device__ float         g_pool [POOL_TOTAL];
static __device__ __nv_bfloat16 g_poolh[2ull * NN16];

// ---------------- helpers ----------------
__device__ __forceinline__ float tanh_fast(float x) {
    float y;
    asm("tanh.approx.f32 %0, %1;" : "=f"(y) : "f"(x));
    return y;
}

__device__ __forceinline__ uint32_t f2tf32(float x) {
    uint32_t u;
    asm("cvt.rna.tf32.f32 %0, %1;" : "=r"(u) : "f"(x));
    return u;
}

__device__ __forceinline__ void mma_tf32(float* c, const uint32_t* a, const uint32_t* b) {
    asm volatile(
        "mma.sync.aligned.m16n8k8.row.col.f32.tf32.tf32.f32 "
        "{%0,%1,%2,%3}, {%4,%5,%6,%7}, {%8,%9}, {%0,%1,%2,%3};"
        : "+f"(c[0]), "+f"(c[1]), "+f"(c[2]), "+f"(c[3])
        : "r"(a[0]), "r"(a[1]), "r"(a[2]), "r"(a[3]), "r"(b[0]), "r"(b[1]));
}

__device__ __forceinline__ void mma16816(float* c, const uint32_t* a, const uint32_t* b) {
    asm volatile(
        "mma.sync.aligned.m16n8k16.row.col.f32.bf16.bf16.f32 "
        "{%0,%1,%2,%3}, {%4,%5,%6,%7}, {%8,%9}, {%0,%1,%2,%3};"
        : "+f"(c[0]), "+f"(c[1]), "+f"(c[2]), "+f"(c[3])
        : "r"(a[0]), "r"(a[1]), "r"(a[2]), "r"(a[3]), "r"(b[0]), "r"(b[1]));
}

__device__ __forceinline__ void cp16(void* smem_dst, const void* gmem_src) {
    uint32_t s = (uint32_t)__cvta_generic_to_shared(smem_dst);
    asm volatile("cp.async.cg.shared.global [%0], [%1], 16;\n" :: "r"(s), "l"(gmem_src));
}
__device__ __forceinline__ void cp_commit() {
    asm volatile("cp.async.commit_group;\n");
}
template<int N>
__device__ __forceinline__ void cp_wait() {
    asm volatile("cp.async.wait_group %0;\n" :: "n"(N));
}

__device__ __forceinline__ void ldsm_x4(uint32_t* r, const void* smem) {
    uint32_t a = (uint32_t)__cvta_generic_to_shared(smem);
    asm volatile("ldmatrix.sync.aligned.m8n8.x4.shared.b16 {%0,%1,%2,%3}, [%4];\n"
        : "=r"(r[0]), "=r"(r[1]), "=r"(r[2]), "=r"(r[3]) : "r"(a));
}
__device__ __forceinline__ void ldsm_x4t(uint32_t* r, const void* smem) {
    uint32_t a = (uint32_t)__cvta_generic_to_shared(smem);
    asm volatile("ldmatrix.sync.aligned.m8n8.x4.trans.shared.b16 {%0,%1,%2,%3}, [%4];\n"
        : "=r"(r[0]), "=r"(r[1]), "=r"(r[2]), "=r"(r[3]) : "r"(a));
}

// =====================================================================
// tf32 tensor-core GEMM, batched. MODE:
//  0: generic  C = alpha * A@B(^T), pool offsets / ext pointers
//  1: AV dual  z<16: yb = softmax(Smix)@v0 ; z>=16: tmp = A1@v1
//  2: QKV fused-scatter: A=x, B = (z? Wqkv1 : Wqkv0), epilogue writes
//     directly into q/k/v [BH][N][DK] layouts
//  3: S dual   z<16: S0 = q0 k0^T /8 ; z>=16: S1 = q1 k1^T /8
// =====================================================================
template<int BN, int WARPS_M, int WARPS_N, bool TRANSB, int MODE>
__global__ __launch_bounds__(256) void gemm_tf32(
    const float* __restrict__ Aext, size_t offA,
    const float* __restrict__ Bext, size_t offB,
    float* __restrict__ Cext, size_t offC,
    int lda, int ldb, int ldc,
    long long sA, long long sB, long long sC,
    int K, float alpha)
{
    constexpr int BM = 128, BK = 32, LDS = BK + 4;     // stride 36
    constexpr int WM = BM / WARPS_M;
    constexpr int WN = BN / WARPS_N;
    constexpr int MT = WM / 16;
    constexpr int NT = WN / 8;
    constexpr int BITERS = BN / 32;

    const float* A;
    const float* B;
    float*       C = nullptr;
    int z = blockIdx.z;
    if (MODE == 1) {
        if (z < 16) {
            A = g_pool + OFF_S0 + (size_t)z * NN;     // softmax(Smix)
            B = g_pool + OFF_V0 + (size_t)z * ND;
            C = g_pool + OFF_YB + (size_t)z * ND;
        } else {
            A = g_pool + OFF_A1 + (size_t)(z - 16) * NN;
            B = g_pool + OFF_V1 + (size_t)(z - 16) * ND;
            C = g_pool + OFF_TMP + (size_t)(z - 16) * ND;
        }
    } else if (MODE == 2) {
        A = Aext;
        B = z ? (const float*)Cext : Bext;   // Wqkv1 smuggled via Cext
    } else if (MODE == 3) {
        int zz = z & 15;
        if (z < 16) {
            A = g_pool + OFF_Q0 + (size_t)zz * ND;
            B = g_pool + OFF_K0 + (size_t)zz * ND;
            C = g_pool + OFF_S0 + (size_t)zz * NN;
        } else {
            A = g_pool + OFF_Q1 + (size_t)zz * ND;
            B = g_pool + OFF_K1 + (size_t)zz * ND;
            C = g_pool + OFF_S1 + (size_t)zz * NN;
        }
    } else {
        A = (Aext ? Aext : (g_pool + offA)) + (size_t)z * (size_t)sA;
        B = (Bext ? Bext : (g_pool + offB)) + (size_t)z * (size_t)sB;
        C = (Cext ? Cext : (g_pool + offC)) + (size_t)z * (size_t)sC;
    }

    __shared__ uint32_t As[BM][LDS];
    __shared__ uint32_t Bs[BN][LDS];   // stored [n][k]

    int tid  = threadIdx.x;
    int warp = tid >> 5, lane = tid & 31;
    int grp  = lane >> 2, kq = lane & 3;
    int bm = blockIdx.y * BM, bn = blockIdx.x * BN;
    int wm = (warp / WARPS_N) * WM, wn = (warp % WARPS_N) * WN;

    float acc[MT][NT][4] = {};

    for (int k0 = 0; k0 < K; k0 += BK) {
        #pragma unroll
        for (int i = 0; i < 4; i++) {
            int linear = i * 256 + tid;
            int r = linear >> 3, c4 = linear & 7;
            float4 v = *(const float4*)&A[(size_t)(bm + r) * lda + k0 + c4 * 4];
            uint4 u = make_uint4(f2tf32(v.x), f2tf32(v.y), f2tf32(v.z), f2tf32(v.w));
            *(uint4*)&As[r][c4 * 4] = u;
        }
        if (TRANSB) {
            #pragma unroll
            for (int i = 0; i < BITERS; i++) {
                int linear = i * 256 + tid;
                int n = linear >> 3, c4 = linear & 7;
                float4 v = *(const float4*)&B[(size_t)(bn + n) * ldb + k0 + c4 * 4];
                uint4 u = make_uint4(f2tf32(v.x), f2tf32(v.y), f2tf32(v.z), f2tf32(v.w));
                *(uint4*)&Bs[n][c4 * 4] = u;
            }
        } else {
            #pragma unroll
            for (int i = 0; i < BITERS; i++) {
                int linear = i * 256 + tid;
                int n4 = linear % (BN / 4), k = linear / (BN / 4);
                float4 v = *(const float4*)&B[(size_t)(k0 + k) * ldb + bn + n4 * 4];
                Bs[n4 * 4 + 0][k] = f2tf32(v.x);
                Bs[n4 * 4 + 1][k] = f2tf32(v.y);
                Bs[n4 * 4 + 2][k] = f2tf32(v.z);
                Bs[n4 * 4 + 3][k] = f2tf32(v.w);
            }
        }
        __syncthreads();

        #pragma unroll
        for (int ks = 0; ks < 4; ks++) {
            int kc = ks * 8 + kq;
            uint32_t a[MT][4], b[NT][2];
            #pragma unroll
            for (int mt = 0; mt < MT; mt++) {
                int r = wm + mt * 16 + grp;
                a[mt][0] = As[r][kc];
                a[mt][1] = As[r + 8][kc];
                a[mt][2] = As[r][kc + 4];
                a[mt][3] = As[r + 8][kc + 4];
            }
            #pragma unroll
            for (int nt = 0; nt < NT; nt++) {
                int n = wn + nt * 8 + grp;
                b[nt][0] = Bs[n][kc];
                b[nt][1] = Bs[n][kc + 4];
            }
            #pragma unroll
            for (int mt = 0; mt < MT; mt++)
                #pragma unroll
                for (int nt = 0; nt < NT; nt++)
                    mma_tf32(acc[mt][nt], a[mt], b[nt]);
        }
        __syncthreads();
    }

    if (MODE == 2) {
        // scatter epilogue: col j -> (s, h, d); row r -> (b, tok)
        size_t qoff = z ? OFF_Q1 : OFF_Q0;
        size_t koff = z ? OFF_K1 : OFF_K0;
        size_t voff = z ? OFF_V1 : OFF_V0;
        #pragma unroll
        for (int mt = 0; mt < MT; mt++) {
            #pragma unroll
            for (int nt = 0; nt < NT; nt++) {
                #pragma unroll
                for (int half = 0; half < 2; half++) {
                    int r  = bm + wm + mt * 16 + grp + half * 8;
                    int cg = bn + wn + nt * 8 + kq * 2;
                    int bb = r >> 10, tok = r & 1023;
                    int s = cg >> 9, h = (cg >> 6) & 7, d = cg & 63;
                    size_t base = (s == 0) ? qoff : (s == 1) ? koff : voff;
                    float2 val = half ? make_float2(acc[mt][nt][2], acc[mt][nt][3])
                                      : make_float2(acc[mt][nt][0], acc[mt][nt][1]);
                    *(float2*)&g_pool[base + ((size_t)(bb * 8 + h) * 1024 + tok) * 64 + d] = val;
                }
            }
        }
        return;
    }

    #pragma unroll
    for (int mt = 0; mt < MT; mt++) {
        #pragma unroll
        for (int nt = 0; nt < NT; nt++) {
            int r = bm + wm + mt * 16 + grp;
            int c = bn + wn + nt * 8 + kq * 2;
            *(float2*)&C[(size_t)r * ldc + c] =
                make_float2(alpha * acc[mt][nt][0], alpha * acc[mt][nt][1]);
            *(float2*)&C[(size_t)(r + 8) * ldc + c] =
                make_float2(alpha * acc[mt][nt][2], alpha * acc[mt][nt][3]);
        }
    }
}

// =====================================================================
// Row softmax over 1024 elems (vectorized). WB=1: also write bf16 copy.
// =====================================================================
template<int WB>
__global__ __launch_bounds__(256) void softmax_rows(size_t inOff, size_t outOff, size_t bfOff)
{
    const float* S = g_pool + inOff;
    float*       A = g_pool + outOff;
    size_t base = (size_t)blockIdx.x * 1024;
    int tid = threadIdx.x;
    int warp = tid >> 5, lane = tid & 31;

    float4 v4 = *(const float4*)&S[base + tid * 4];
    float v[4] = { v4.x, v4.y, v4.z, v4.w };
    float mx = fmaxf(fmaxf(v[0], v[1]), fmaxf(v[2], v[3]));
    #pragma unroll
    for (int o = 16; o > 0; o >>= 1) mx = fmaxf(mx, __shfl_xor_sync(0xffffffffu, mx, o));
    __shared__ float red[8];
    if (lane == 0) red[warp] = mx;
    __syncthreads();
    float mAll = red[0];
    #pragma unroll
    for (int w = 1; w < 8; w++) mAll = fmaxf(mAll, red[w]);
    __syncthreads();

    float e[4], s = 0.f;
    #pragma unroll
    for (int i = 0; i < 4; i++) { e[i] = __expf(v[i] - mAll); s += e[i]; }
    #pragma unroll
    for (int o = 16; o > 0; o >>= 1) s += __shfl_xor_sync(0xffffffffu, s, o);
    if (lane == 0) red[warp] = s;
    __syncthreads();
    float tot = 0.f;
    #pragma unroll
    for (int w = 0; w < 8; w++) tot += red[w];
    float inv = __fdividef(1.0f, tot);

    float p[4];
    #pragma unroll
    for (int i = 0; i < 4; i++) p[i] = e[i] * inv;
    *(float4*)&A[base + tid * 4] = make_float4(p[0], p[1], p[2], p[3]);
    if (WB) {
        __nv_bfloat162 lo = __floats2bfloat162_rn(p[0], p[1]);
        __nv_bfloat162 hi = __floats2bfloat162_rn(p[2], p[3]);
        *(uint32_t*)&g_poolh[bfOff + base + tid * 4] = *(uint32_t*)&lo;
        *(uint32_t*)&g_poolh[bfOff + base + tid * 4 + 2] = *(uint32_t*)&hi;
    }
}

// =====================================================================
// Chain GEMM v5: bf16 mma.sync, 2-stage cp.async, BK=64, 2 CTAs/SM.
// z<16: Cf[z] = A0h[z] @ A1h[z];  z>=16: Cb[z-16] = A1h[z-16] @ A0h[z-16].
// CTA 128x128, 8 warps (2x4), warp tile 64x32.
// Dynamic smem: 2 stages x (As 128x72 + Bs 64x136) bf16 = 71,680 B.
// =====================================================================
#define CH_ASTR 72
#define CH_BSTR 136
#define CH_AELEM (128 * CH_ASTR)            // 9216
#define CH_BELEM (64 * CH_BSTR)             // 8704
#define CH_STAGE (CH_AELEM + CH_BELEM)      // 17920 elems
#define CH_SMEM  (2 * CH_STAGE * 2)         // 71,680 bytes

__global__ __launch_bounds__(256, 2) void gemm_chain_v5() {
    extern __shared__ __nv_bfloat16 sm[];

    int z = blockIdx.z;
    const __nv_bfloat16 *A, *B;
    float* C;
    if (z < 16) {
        A = g_poolh + OFF_A0H + (size_t)z * NN;
        B = g_poolh + OFF_A1H + (size_t)z * NN;
        C = g_pool  + OFF_CF  + (size_t)z * NN;
    } else {
        int zz = z - 16;
        A = g_poolh + OFF_A1H + (size_t)zz * NN;
        B = g_poolh + OFF_A0H + (size_t)zz * NN;
        C = g_pool  + OFF_CB  + (size_t)zz * NN;
    }

    int tid = threadIdx.x, warp = tid >> 5, lane = tid & 31;
    int bm = blockIdx.y * 128, bn = blockIdx.x * 128;
    int wm = (warp >> 2) * 64, wn = (warp & 3) * 32;

    auto load_stage = [&](int chunk, int s) {
        __nv_bfloat16* Ab = sm + s * CH_STAGE;
        __nv_bfloat16* Bb = Ab + CH_AELEM;
        int k0 = chunk * 64;
        #pragma unroll
        for (int i = 0; i < 4; i++) {
            int idx = i * 256 + tid;
            int r = idx >> 3, c16 = idx & 7;        // A: 128 rows x 8 chunks
            cp16(Ab + r * CH_ASTR + c16 * 8,
                 A + (size_t)(bm + r) * 1024 + k0 + c16 * 8);
        }
        #pragma unroll
        for (int i = 0; i < 4; i++) {
            int idx = i * 256 + tid;
            int k = idx >> 4, c16 = idx & 15;       // B: 64 k-rows x 16 chunks
            cp16(Bb + k * CH_BSTR + c16 * 8,
                 B + (size_t)(k0 + k) * 1024 + bn + c16 * 8);
        }
    };

    float acc[4][4][4] = {};

    load_stage(0, 0); cp_commit();

    for (int c = 0; c < 16; c++) {
        cp_wait<0>();
        __syncthreads();

        if (c + 1 < 16) { load_stage(c + 1, (c + 1) & 1); cp_commit(); }

        const __nv_bfloat16* Ab = sm + (c & 1) * CH_STAGE;
        const __nv_bfloat16* Bb = Ab + CH_AELEM;

        #pragma unroll
        for (int ks = 0; ks < 4; ks++) {
            int kb = ks * 16;
            uint32_t a[4][4], b[4][2];
            #pragma unroll
            for (int mt = 0; mt < 4; mt++)
                ldsm_x4(a[mt], Ab + (wm + mt * 16 + (lane & 15)) * CH_ASTR
                                  + kb + ((lane >> 4) << 3));
            #pragma unroll
            for (int p = 0; p < 2; p++) {
                uint32_t r[4];
                ldsm_x4t(r, Bb + (kb + (lane & 7) + (((lane >> 3) & 1) << 3)) * CH_BSTR
                               + wn + p * 16 + ((lane >> 4) << 3));
                b[2 * p][0] = r[0]; b[2 * p][1] = r[1];
                b[2 * p + 1][0] = r[2]; b[2 * p + 1][1] = r[3];
            }
            #pragma unroll
            for (int mt = 0; mt < 4; mt++)
                #pragma unroll
                for (int nt = 0; nt < 4; nt++)
                    mma16816(acc[mt][nt], a[mt], b[nt]);
        }
        __syncthreads();   // all warps done with this buffer before next overwrite
    }

    #pragma unroll
    for (int mt = 0; mt < 4; mt++) {
        #pragma unroll
        for (int nt = 0; nt < 4; nt++) {
            int r = bm + wm + mt * 16 + (lane >> 2);
            int cc = bn + wn + nt * 8 + (lane & 3) * 2;
            *(float2*)&C[(size_t)r * 1024 + cc]       = make_float2(acc[mt][nt][0], acc[mt][nt][1]);
            *(float2*)&C[(size_t)(r + 8) * 1024 + cc] = make_float2(acc[mt][nt][2], acc[mt][nt][3]);
        }
    }
}

// =====================================================================
// Fused: feat -> conv1+gelu -> conv2+sigmoid -> gates -> Smix (in Cb).
// =====================================================================
__global__ __launch_bounds__(256) void fuse_kernel(
    const float* __restrict__ w1, const float* __restrict__ b1,
    const float* __restrict__ w2, const float* __restrict__ b2)
{
    __shared__ float s0t[32][33], s1t[32][33];
    __shared__ float w1s[16][6], b1s[16], w2s[4][16], b2s[4];

    size_t off = (size_t)blockIdx.z * NN;
    int m0 = blockIdx.y * 32, n0 = blockIdx.x * 32;
    int tid = threadIdx.x;
    int tx = tid & 31, ty = tid >> 5;

    if (tid < 96)       ((float*)w1s)[tid]        = w1[tid];
    else if (tid < 112) b1s[tid - 96]             = b1[tid - 96];
    else if (tid < 176) ((float*)w2s)[tid - 112]  = w2[tid - 112];
    else if (tid < 180) b2s[tid - 176]            = b2[tid - 176];

    const float* S0 = g_pool + OFF_S0;
    const float* S1 = g_pool + OFF_S1;
    const float* Cf = g_pool + OFF_CF;
    float*       Cb = g_pool + OFF_CB;

    #pragma unroll
    for (int r = 0; r < 4; r++) {
        int rr = ty + r * 8;
        s0t[rr][tx] = S0[off + (size_t)(n0 + rr) * 1024 + m0 + tx];
        s1t[rr][tx] = S1[off + (size_t)(n0 + rr) * 1024 + m0 + tx];
    }
    __syncthreads();

    #pragma unroll
    for (int r = 0; r < 4; r++) {
        int row = ty + r * 8;
        size_t gidx = off + (size_t)(m0 + row) * 1024 + n0 + tx;
        float s0 = S0[gidx], s1 = S1[gidx];
        float f2 = s0t[tx][row];   // S0^T
        float f3 = s1t[tx][row];   // S1^T
        float cr = __logf(Cf[gidx] + 1e-6f);
        float cl = __logf(Cb[gidx] + 1e-6f);
        float f[6] = { s0, s1, f2, f3, cr, cl };

        float g[4];
        #pragma unroll
        for (int o = 0; o < 4; o++) g[o] = b2s[o];

        #pragma unroll
        for (int oh = 0; oh < 16; oh++) {
            float a = b1s[oh];
            #pragma unroll
            for (int c = 0; c < 6; c++) a += w1s[oh][c] * f[c];
            float gx = 0.7978845608028654f * (a + 0.044715f * a * a * a);
            float hg = 0.5f * a * (1.0f + tanh_fast(gx));
            #pragma unroll
            for (int o = 0; o < 4; o++) g[o] += w2s[o][oh] * hg;
        }
        #pragma unroll
        for (int o = 0; o < 4; o++) g[o] = __fdividef(1.0f, 1.0f + __expf(-g[o]));

        float d   = fabsf(s0 - s1);
        float lse = fmaxf(s0, s1) + __logf(1.0f + __expf(-d));
        float smix = s0 + g[0] * s1 + g[1] * (lse - s0) - g[2] * (0.5f * s1) + g[3] * cr;
        Cb[gidx] = smix;
    }
}

// =====================================================================
// Combine: Y[b][tok][h*64+d] = yb + sigmoid(cvl) * ych
// =====================================================================
__global__ void combine_kernel(const float* __restrict__ cvl) {
    int idx = blockIdx.x * 256 + threadIdx.x;
    if (idx >= (int)(BH * ND)) return;
    int bh  = idx >> 16;
    int rr  = idx & 65535;
    int tok = rr >> 6;
    int d   = rr & 63;
    int b = bh >> 3, h = bh & 7;
    float sig = __fdividef(1.0f, 1.0f + __expf(-cvl[0]));
    float y = g_pool[OFF_YB + (size_t)idx] + sig * g_pool[OFF_YCH + (size_t)idx];
    g_pool[OFF_Y + ((size_t)(b * 1024 + tok)) * 512 + h * 64 + d] = y;
}

// =====================================================================
// Host launch sequence
// =====================================================================
extern "C" void kernel_launch(void* const* d_in, const int* in_sizes, int n_in,
                              void* d_out, int out_size)
{
    const float* x     = (const float*)d_in[0];
    const float* Wqkv0 = (const float*)d_in[1];
    const float* Wqkv1 = (const float*)d_in[2];
    const float* Wproj = (const float*)d_in[3];
    const float* c1w   = (const float*)d_in[4];
    const float* c1b   = (const float*)d_in[5];
    const float* c2w   = (const float*)d_in[6];
    const float* c2b   = (const float*)d_in[7];
    const float* cvl   = (const float*)d_in[8];
    float* out = (float*)d_out;

    cudaFuncSetAttribute(gemm_chain_v5,
                         cudaFuncAttributeMaxDynamicSharedMemorySize, CH_SMEM);

    // 1) qkv GEMMs, both weight sets, scattered epilogue (one launch, z=2)
    gemm_tf32<128, 2, 4, false, 2><<<dim3(12, 16, 2), 256>>>(x, 0, Wqkv0, 0,
        (float*)Wqkv1, 0, 512, 1536, 0, 0, 0, 0, 512, 1.0f);

    // 2) S0 + S1 (one launch, z=32)
    gemm_tf32<128, 2, 4, true, 3><<<dim3(8, 8, 32), 256>>>(nullptr, 0, nullptr, 0,
        nullptr, 0, 64, 64, 1024, 0, 0, 0, 64, 0.125f);

    // 3) softmaxes (+bf16 copies)
    softmax_rows<1><<<16384, 256>>>(OFF_S0, OFF_A0, OFF_A0H);
    softmax_rows<1><<<16384, 256>>>(OFF_S1, OFF_A1, OFF_A1H);

    // 4) C_fwd / C_bwd (bf16 mma, 2-stage, 2 CTAs/SM)
    gemm_chain_v5<<<dim3(8, 8, 32), 256, CH_SMEM>>>();

    // 5) fused feat/conv/gates/Smix
    fuse_kernel<<<dim3(32, 32, 16), 256>>>(c1w, c1b, c2w, c2b);

    // 6) A = softmax(Smix) -> S0 buffer
    softmax_rows<0><<<16384, 256>>>(OFF_CB, OFF_S0, 0);

    // 7) yb = A @ v0 and tmp = A1 @ v1 in ONE launch (z=32)
    gemm_tf32<64, 4, 2, false, 1><<<dim3(1, 8, 32), 256>>>(nullptr, 0, nullptr, 0,
        nullptr, 0, 1024, 64, 64, 0, 0, 0, 1024, 1.0f);

    // 8) ych = A0 @ tmp
    gemm_tf32<64, 4, 2, false, 0><<<dim3(1, 8, 16), 256>>>(nullptr, OFF_A0, nullptr, OFF_TMP,
        nullptr, OFF_YCH, 1024, 64, 64, (long long)NN, (long long)ND, (long long)ND, 1024, 1.0f);

    // 9) combine into Y
    combine_kernel<<<(BH * ND + 255) / 256, 256>>>(cvl);

    // 10) out = Y @ Wproj (tf32 TC)
    gemm_tf32<128, 2, 4, false, 0><<<dim3(4, 16, 1), 256>>>(nullptr, OFF_Y, Wproj, 0, out, 0,
        512, 512, 512, 0, 0, 0, 512, 1.0f);

    (void)in_sizes; (void)n_in; (void)out_size;
}

// round 11
// speedup vs baseline: 1.1769x; 1.0759x over previous
#include <cuda_runtime.h>
#include <cuda_bf16.h>
#include <cstdint>

// ---------------- problem constants ----------------
#define BATCH   2
#define NSEQ    1024
#define DIMF    512
#define HEADS   8
#define DKH     64
#define BH      16              // BATCH*HEADS
#define NN      1048576ull      // NSEQ*NSEQ
#define ND      65536ull        // NSEQ*DKH
#define NN16    16777216ull     // BH*NN

// ---------------- scratch pool (static device memory; allocation-free) -----
#define OFF_Q0  0ull
#define OFF_K0  1048576ull
#define OFF_V0  2097152ull
#define OFF_Q1  3145728ull
#define OFF_K1  4194304ull
#define OFF_V1  5242880ull
#define OFF_S0  6291456ull
#define OFF_S1  (OFF_S0 + NN16)
#define OFF_CF  (OFF_S1 + NN16)
#define OFF_CB  (OFF_CF + NN16)
#define OFF_TMP (OFF_CB + NN16)
#define OFF_YCH (OFF_TMP + 1048576ull)
#define OFF_YB  (OFF_YCH + 1048576ull)
#define OFF_Y   (OFF_YB  + 1048576ull)
#define POOL_TOTAL (OFF_Y + 1048576ull)

#define OFF_A0H 0ull
#define OFF_A1H NN16

static __device__ float         g_pool [POOL_TOTAL];
static __device__ __nv_bfloat16 g_poolh[2ull * NN16];

// ---------------- helpers ----------------
__device__ __forceinline__ float tanh_fast(float x) {
    float y;
    asm("tanh.approx.f32 %0, %1;" : "=f"(y) : "f"(x));
    return y;
}

__device__ __forceinline__ uint32_t f2tf32(float x) {
    uint32_t u;
    asm("cvt.rna.tf32.f32 %0, %1;" : "=r"(u) : "f"(x));
    return u;
}

__device__ __forceinline__ void mma_tf32(float* c, const uint32_t* a, const uint32_t* b) {
    asm volatile(
        "mma.sync.aligned.m16n8k8.row.col.f32.tf32.tf32.f32 "
        "{%0,%1,%2,%3}, {%4,%5,%6,%7}, {%8,%9}, {%0,%1,%2,%3};"
        : "+f"(c[0]), "+f"(c[1]), "+f"(c[2]), "+f"(c[3])
        : "r"(a[0]), "r"(a[1]), "r"(a[2]), "r"(a[3]), "r"(b[0]), "r"(b[1]));
}

__device__ __forceinline__ void mma16816(float* c, const uint32_t* a, const uint32_t* b) {
    asm volatile(
        "mma.sync.aligned.m16n8k16.row.col.f32.bf16.bf16.f32 "
        "{%0,%1,%2,%3}, {%4,%5,%6,%7}, {%8,%9}, {%0,%1,%2,%3};"
        : "+f"(c[0]), "+f"(c[1]), "+f"(c[2]), "+f"(c[3])
        : "r"(a[0]), "r"(a[1]), "r"(a[2]), "r"(a[3]), "r"(b[0]), "r"(b[1]));
}

__device__ __forceinline__ void cp16(void* smem_dst, const void* gmem_src) {
    uint32_t s = (uint32_t)__cvta_generic_to_shared(smem_dst);
    asm volatile("cp.async.cg.shared.global [%0], [%1], 16;\n" :: "r"(s), "l"(gmem_src));
}
__device__ __forceinline__ void cp_commit() {
    asm volatile("cp.async.commit_group;\n");
}
template<int N>
__device__ __forceinline__ void cp_wait() {
    asm volatile("cp.async.wait_group %0;\n" :: "n"(N));
}

__device__ __forceinline__ void ldsm_x4(uint32_t* r, const void* smem) {
    uint32_t a = (uint32_t)__cvta_generic_to_shared(smem);
    asm volatile("ldmatrix.sync.aligned.m8n8.x4.shared.b16 {%0,%1,%2,%3}, [%4];\n"
        : "=r"(r[0]), "=r"(r[1]), "=r"(r[2]), "=r"(r[3]) : "r"(a));
}
__device__ __forceinline__ void ldsm_x4t(uint32_t* r, const void* smem) {
    uint32_t a = (uint32_t)__cvta_generic_to_shared(smem);
    asm volatile("ldmatrix.sync.aligned.m8n8.x4.trans.shared.b16 {%0,%1,%2,%3}, [%4];\n"
        : "=r"(r[0]), "=r"(r[1]), "=r"(r[2]), "=r"(r[3]) : "r"(a));
}

// =====================================================================
// tf32 tensor-core GEMM, batched. MODE:
//  0: generic  C = alpha * A@B(^T), pool offsets / ext pointers
//  1: AV dual  z<16: yb = softmax(Smix)@v0 ; z>=16: ych = Cf@v1
//  2: QKV fused-scatter: A=x, B = (z? Wqkv1 : Wqkv0), epilogue writes
//     directly into q/k/v [BH][N][DK] layouts
//  3: S dual   z<16: S0 = q0 k0^T /8 ; z>=16: S1 = q1 k1^T /8
// =====================================================================
template<int BN, int WARPS_M, int WARPS_N, bool TRANSB, int MODE>
__global__ __launch_bounds__(256) void gemm_tf32(
    const float* __restrict__ Aext, size_t offA,
    const float* __restrict__ Bext, size_t offB,
    float* __restrict__ Cext, size_t offC,
    int lda, int ldb, int ldc,
    long long sA, long long sB, long long sC,
    int K, float alpha)
{
    constexpr int BM = 128, BK = 32, LDS = BK + 4;     // stride 36
    constexpr int WM = BM / WARPS_M;
    constexpr int WN = BN / WARPS_N;
    constexpr int MT = WM / 16;
    constexpr int NT = WN / 8;
    constexpr int BITERS = BN / 32;

    const float* A;
    const float* B;
    float*       C = nullptr;
    int z = blockIdx.z;
    if (MODE == 1) {
        if (z < 16) {
            A = g_pool + OFF_S0 + (size_t)z * NN;     // softmax(Smix)
            B = g_pool + OFF_V0 + (size_t)z * ND;
            C = g_pool + OFF_YB + (size_t)z * ND;
        } else {
            A = g_pool + OFF_CF + (size_t)(z - 16) * NN;   // ych = Cf @ v1
            B = g_pool + OFF_V1 + (size_t)(z - 16) * ND;
            C = g_pool + OFF_YCH + (size_t)(z - 16) * ND;
        }
    } else if (MODE == 2) {
        A = Aext;
        B = z ? (const float*)Cext : Bext;   // Wqkv1 smuggled via Cext
    } else if (MODE == 3) {
        int zz = z & 15;
        if (z < 16) {
            A = g_pool + OFF_Q0 + (size_t)zz * ND;
            B = g_pool + OFF_K0 + (size_t)zz * ND;
            C = g_pool + OFF_S0 + (size_t)zz * NN;
        } else {
            A = g_pool + OFF_Q1 + (size_t)zz * ND;
            B = g_pool + OFF_K1 + (size_t)zz * ND;
            C = g_pool + OFF_S1 + (size_t)zz * NN;
        }
    } else {
        A = (Aext ? Aext : (g_pool + offA)) + (size_t)z * (size_t)sA;
        B = (Bext ? Bext : (g_pool + offB)) + (size_t)z * (size_t)sB;
        C = (Cext ? Cext : (g_pool + offC)) + (size_t)z * (size_t)sC;
    }

    __shared__ uint32_t As[BM][LDS];
    __shared__ uint32_t Bs[BN][LDS];   // stored [n][k]

    int tid  = threadIdx.x;
    int warp = tid >> 5, lane = tid & 31;
    int grp  = lane >> 2, kq = lane & 3;
    int bm = blockIdx.y * BM, bn = blockIdx.x * BN;
    int wm = (warp / WARPS_N) * WM, wn = (warp % WARPS_N) * WN;

    float acc[MT][NT][4] = {};

    for (int k0 = 0; k0 < K; k0 += BK) {
        #pragma unroll
        for (int i = 0; i < 4; i++) {
            int linear = i * 256 + tid;
            int r = linear >> 3, c4 = linear & 7;
            float4 v = *(const float4*)&A[(size_t)(bm + r) * lda + k0 + c4 * 4];
            uint4 u = make_uint4(f2tf32(v.x), f2tf32(v.y), f2tf32(v.z), f2tf32(v.w));
            *(uint4*)&As[r][c4 * 4] = u;
        }
        if (TRANSB) {
            #pragma unroll
            for (int i = 0; i < BITERS; i++) {
                int linear = i * 256 + tid;
                int n = linear >> 3, c4 = linear & 7;
                float4 v = *(const float4*)&B[(size_t)(bn + n) * ldb + k0 + c4 * 4];
                uint4 u = make_uint4(f2tf32(v.x), f2tf32(v.y), f2tf32(v.z), f2tf32(v.w));
                *(uint4*)&Bs[n][c4 * 4] = u;
            }
        } else {
            #pragma unroll
            for (int i = 0; i < BITERS; i++) {
                int linear = i * 256 + tid;
                int n4 = linear % (BN / 4), k = linear / (BN / 4);
                float4 v = *(const float4*)&B[(size_t)(k0 + k) * ldb + bn + n4 * 4];
                Bs[n4 * 4 + 0][k] = f2tf32(v.x);
                Bs[n4 * 4 + 1][k] = f2tf32(v.y);
                Bs[n4 * 4 + 2][k] = f2tf32(v.z);
                Bs[n4 * 4 + 3][k] = f2tf32(v.w);
            }
        }
        __syncthreads();

        #pragma unroll
        for (int ks = 0; ks < 4; ks++) {
            int kc = ks * 8 + kq;
            uint32_t a[MT][4], b[NT][2];
            #pragma unroll
            for (int mt = 0; mt < MT; mt++) {
                int r = wm + mt * 16 + grp;
                a[mt][0] = As[r][kc];
                a[mt][1] = As[r + 8][kc];
                a[mt][2] = As[r][kc + 4];
                a[mt][3] = As[r + 8][kc + 4];
            }
            #pragma unroll
            for (int nt = 0; nt < NT; nt++) {
                int n = wn + nt * 8 + grp;
                b[nt][0] = Bs[n][kc];
                b[nt][1] = Bs[n][kc + 4];
            }
            #pragma unroll
            for (int mt = 0; mt < MT; mt++)
                #pragma unroll
                for (int nt = 0; nt < NT; nt++)
                    mma_tf32(acc[mt][nt], a[mt], b[nt]);
        }
        __syncthreads();
    }

    if (MODE == 2) {
        // scatter epilogue: col j -> (s, h, d); row r -> (b, tok)
        size_t qoff = z ? OFF_Q1 : OFF_Q0;
        size_t koff = z ? OFF_K1 : OFF_K0;
        size_t voff = z ? OFF_V1 : OFF_V0;
        #pragma unroll
        for (int mt = 0; mt < MT; mt++) {
            #pragma unroll
            for (int nt = 0; nt < NT; nt++) {
                #pragma unroll
                for (int half = 0; half < 2; half++) {
                    int r  = bm + wm + mt * 16 + grp + half * 8;
                    int cg = bn + wn + nt * 8 + kq * 2;
                    int bb = r >> 10, tok = r & 1023;
                    int s = cg >> 9, h = (cg >> 6) & 7, d = cg & 63;
                    size_t base = (s == 0) ? qoff : (s == 1) ? koff : voff;
                    float2 val = half ? make_float2(acc[mt][nt][2], acc[mt][nt][3])
                                      : make_float2(acc[mt][nt][0], acc[mt][nt][1]);
                    *(float2*)&g_pool[base + ((size_t)(bb * 8 + h) * 1024 + tok) * 64 + d] = val;
                }
            }
        }
        return;
    }

    #pragma unroll
    for (int mt = 0; mt < MT; mt++) {
        #pragma unroll
        for (int nt = 0; nt < NT; nt++) {
            int r = bm + wm + mt * 16 + grp;
            int c = bn + wn + nt * 8 + kq * 2;
            *(float2*)&C[(size_t)r * ldc + c] =
                make_float2(alpha * acc[mt][nt][0], alpha * acc[mt][nt][1]);
            *(float2*)&C[(size_t)(r + 8) * ldc + c] =
                make_float2(alpha * acc[mt][nt][2], alpha * acc[mt][nt][3]);
        }
    }
}

// =====================================================================
// Row softmax over 1024 elems (vectorized).
// WB=0: fp32 out only.  WB=2: bf16 out ONLY (batched over z: in/bf
// offsets advance by NN16 per blockIdx.z).
// =====================================================================
template<int WB>
__global__ __launch_bounds__(256) void softmax_rows(size_t inOff, size_t outOff, size_t bfOff)
{
    size_t zoff = (WB == 2) ? (size_t)blockIdx.z * NN16 : 0;
    const float* S = g_pool + inOff + zoff;
    size_t base = (size_t)blockIdx.x * 1024;
    int tid = threadIdx.x;
    int warp = tid >> 5, lane = tid & 31;

    float4 v4 = *(const float4*)&S[base + tid * 4];
    float v[4] = { v4.x, v4.y, v4.z, v4.w };
    float mx = fmaxf(fmaxf(v[0], v[1]), fmaxf(v[2], v[3]));
    #pragma unroll
    for (int o = 16; o > 0; o >>= 1) mx = fmaxf(mx, __shfl_xor_sync(0xffffffffu, mx, o));
    __shared__ float red[8];
    if (lane == 0) red[warp] = mx;
    __syncthreads();
    float mAll = red[0];
    #pragma unroll
    for (int w = 1; w < 8; w++) mAll = fmaxf(mAll, red[w]);
    __syncthreads();

    float e[4], s = 0.f;
    #pragma unroll
    for (int i = 0; i < 4; i++) { e[i] = __expf(v[i] - mAll); s += e[i]; }
    #pragma unroll
    for (int o = 16; o > 0; o >>= 1) s += __shfl_xor_sync(0xffffffffu, s, o);
    if (lane == 0) red[warp] = s;
    __syncthreads();
    float tot = 0.f;
    #pragma unroll
    for (int w = 0; w < 8; w++) tot += red[w];
    float inv = __fdividef(1.0f, tot);

    float p[4];
    #pragma unroll
    for (int i = 0; i < 4; i++) p[i] = e[i] * inv;
    if (WB == 0) {
        float* A = g_pool + outOff;
        *(float4*)&A[base + tid * 4] = make_float4(p[0], p[1], p[2], p[3]);
    } else {
        __nv_bfloat162 lo = __floats2bfloat162_rn(p[0], p[1]);
        __nv_bfloat162 hi = __floats2bfloat162_rn(p[2], p[3]);
        *(uint32_t*)&g_poolh[bfOff + zoff + base + tid * 4] = *(uint32_t*)&lo;
        *(uint32_t*)&g_poolh[bfOff + zoff + base + tid * 4 + 2] = *(uint32_t*)&hi;
    }
}

// =====================================================================
// Chain GEMM v5: bf16 mma.sync, 2-stage cp.async, BK=64, 2 CTAs/SM.
// z<16: Cf[z] = A0h[z] @ A1h[z];  z>=16: Cb[z-16] = A1h[z-16] @ A0h[z-16].
// CTA 128x128, 8 warps (2x4), warp tile 64x32.
// Dynamic smem: 2 stages x (As 128x72 + Bs 64x136) bf16 = 71,680 B.
// =====================================================================
#define CH_ASTR 72
#define CH_BSTR 136
#define CH_AELEM (128 * CH_ASTR)            // 9216
#define CH_BELEM (64 * CH_BSTR)             // 8704
#define CH_STAGE (CH_AELEM + CH_BELEM)      // 17920 elems
#define CH_SMEM  (2 * CH_STAGE * 2)         // 71,680 bytes

__global__ __launch_bounds__(256, 2) void gemm_chain_v5() {
    extern __shared__ __nv_bfloat16 sm[];

    int z = blockIdx.z;
    const __nv_bfloat16 *A, *B;
    float* C;
    if (z < 16) {
        A = g_poolh + OFF_A0H + (size_t)z * NN;
        B = g_poolh + OFF_A1H + (size_t)z * NN;
        C = g_pool  + OFF_CF  + (size_t)z * NN;
    } else {
        int zz = z - 16;
        A = g_poolh + OFF_A1H + (size_t)zz * NN;
        B = g_poolh + OFF_A0H + (size_t)zz * NN;
        C = g_pool  + OFF_CB  + (size_t)zz * NN;
    }

    int tid = threadIdx.x, warp = tid >> 5, lane = tid & 31;
    int bm = blockIdx.y * 128, bn = blockIdx.x * 128;
    int wm = (warp >> 2) * 64, wn = (warp & 3) * 32;

    auto load_stage = [&](int chunk, int s) {
        __nv_bfloat16* Ab = sm + s * CH_STAGE;
        __nv_bfloat16* Bb = Ab + CH_AELEM;
        int k0 = chunk * 64;
        #pragma unroll
        for (int i = 0; i < 4; i++) {
            int idx = i * 256 + tid;
            int r = idx >> 3, c16 = idx & 7;        // A: 128 rows x 8 chunks
            cp16(Ab + r * CH_ASTR + c16 * 8,
                 A + (size_t)(bm + r) * 1024 + k0 + c16 * 8);
        }
        #pragma unroll
        for (int i = 0; i < 4; i++) {
            int idx = i * 256 + tid;
            int k = idx >> 4, c16 = idx & 15;       // B: 64 k-rows x 16 chunks
            cp16(Bb + k * CH_BSTR + c16 * 8,
                 B + (size_t)(k0 + k) * 1024 + bn + c16 * 8);
        }
    };

    float acc[4][4][4] = {};

    load_stage(0, 0); cp_commit();

    for (int c = 0; c < 16; c++) {
        cp_wait<0>();
        __syncthreads();

        if (c + 1 < 16) { load_stage(c + 1, (c + 1) & 1); cp_commit(); }

        const __nv_bfloat16* Ab = sm + (c & 1) * CH_STAGE;
        const __nv_bfloat16* Bb = Ab + CH_AELEM;

        #pragma unroll
        for (int ks = 0; ks < 4; ks++) {
            int kb = ks * 16;
            uint32_t a[4][4], b[4][2];
            #pragma unroll
            for (int mt = 0; mt < 4; mt++)
                ldsm_x4(a[mt], Ab + (wm + mt * 16 + (lane & 15)) * CH_ASTR
                                  + kb + ((lane >> 4) << 3));
            #pragma unroll
            for (int p = 0; p < 2; p++) {
                uint32_t r[4];
                ldsm_x4t(r, Bb + (kb + (lane & 7) + (((lane >> 3) & 1) << 3)) * CH_BSTR
                               + wn + p * 16 + ((lane >> 4) << 3));
                b[2 * p][0] = r[0]; b[2 * p][1] = r[1];
                b[2 * p + 1][0] = r[2]; b[2 * p + 1][1] = r[3];
            }
            #pragma unroll
            for (int mt = 0; mt < 4; mt++)
                #pragma unroll
                for (int nt = 0; nt < 4; nt++)
                    mma16816(acc[mt][nt], a[mt], b[nt]);
        }
        __syncthreads();   // all warps done with this buffer before next overwrite
    }

    #pragma unroll
    for (int mt = 0; mt < 4; mt++) {
        #pragma unroll
        for (int nt = 0; nt < 4; nt++) {
            int r = bm + wm + mt * 16 + (lane >> 2);
            int cc = bn + wn + nt * 8 + (lane & 3) * 2;
            *(float2*)&C[(size_t)r * 1024 + cc]       = make_float2(acc[mt][nt][0], acc[mt][nt][1]);
            *(float2*)&C[(size_t)(r + 8) * 1024 + cc] = make_float2(acc[mt][nt][2], acc[mt][nt][3]);
        }
    }
}

// =====================================================================
// Fused: feat -> conv1+gelu -> conv2+sigmoid -> gates -> Smix (in Cb).
// =====================================================================
__global__ __launch_bounds__(256) void fuse_kernel(
    const float* __restrict__ w1, const float* __restrict__ b1,
    const float* __restrict__ w2, const float* __restrict__ b2)
{
    __shared__ float s0t[32][33], s1t[32][33];
    __shared__ float w1s[16][6], b1s[16], w2s[4][16], b2s[4];

    size_t off = (size_t)blockIdx.z * NN;
    int m0 = blockIdx.y * 32, n0 = blockIdx.x * 32;
    int tid = threadIdx.x;
    int tx = tid & 31, ty = tid >> 5;

    if (tid < 96)       ((float*)w1s)[tid]        = w1[tid];
    else if (tid < 112) b1s[tid - 96]             = b1[tid - 96];
    else if (tid < 176) ((float*)w2s)[tid - 112]  = w2[tid - 112];
    else if (tid < 180) b2s[tid - 176]            = b2[tid - 176];

    const float* S0 = g_pool + OFF_S0;
    const float* S1 = g_pool + OFF_S1;
    const float* Cf = g_pool + OFF_CF;
    float*       Cb = g_pool + OFF_CB;

    #pragma unroll
    for (int r = 0; r < 4; r++) {
        int rr = ty + r * 8;
        s0t[rr][tx] = S0[off + (size_t)(n0 + rr) * 1024 + m0 + tx];
        s1t[rr][tx] = S1[off + (size_t)(n0 + rr) * 1024 + m0 + tx];
    }
    __syncthreads();

    #pragma unroll
    for (int r = 0; r < 4; r++) {
        int row = ty + r * 8;
        size_t gidx = off + (size_t)(m0 + row) * 1024 + n0 + tx;
        float s0 = S0[gidx], s1 = S1[gidx];
        float f2 = s0t[tx][row];   // S0^T
        float f3 = s1t[tx][row];   // S1^T
        float cr = __logf(Cf[gidx] + 1e-6f);
        float cl = __logf(Cb[gidx] + 1e-6f);
        float f[6] = { s0, s1, f2, f3, cr, cl };

        float g[4];
        #pragma unroll
        for (int o = 0; o < 4; o++) g[o] = b2s[o];

        #pragma unroll
        for (int oh = 0; oh < 16; oh++) {
            float a = b1s[oh];
            #pragma unroll
            for (int c = 0; c < 6; c++) a += w1s[oh][c] * f[c];
            float gx = 0.7978845608028654f * (a + 0.044715f * a * a * a);
            float hg = 0.5f * a * (1.0f + tanh_fast(gx));
            #pragma unroll
            for (int o = 0; o < 4; o++) g[o] += w2s[o][oh] * hg;
        }
        #pragma unroll
        for (int o = 0; o < 4; o++) g[o] = __fdividef(1.0f, 1.0f + __expf(-g[o]));

        float d   = fabsf(s0 - s1);
        float lse = fmaxf(s0, s1) + __logf(1.0f + __expf(-d));
        float smix = s0 + g[0] * s1 + g[1] * (lse - s0) - g[2] * (0.5f * s1) + g[3] * cr;
        Cb[gidx] = smix;
    }
}

// =====================================================================
// Combine: Y[b][tok][h*64+d] = yb + sigmoid(cvl) * ych
// =====================================================================
__global__ void combine_kernel(const float* __restrict__ cvl) {
    int idx = blockIdx.x * 256 + threadIdx.x;
    if (idx >= (int)(BH * ND)) return;
    int bh  = idx >> 16;
    int rr  = idx & 65535;
    int tok = rr >> 6;
    int d   = rr & 63;
    int b = bh >> 3, h = bh & 7;
    float sig = __fdividef(1.0f, 1.0f + __expf(-cvl[0]));
    float y = g_pool[OFF_YB + (size_t)idx] + sig * g_pool[OFF_YCH + (size_t)idx];
    g_pool[OFF_Y + ((size_t)(b * 1024 + tok)) * 512 + h * 64 + d] = y;
}

// =====================================================================
// Host launch sequence
// =====================================================================
extern "C" void kernel_launch(void* const* d_in, const int* in_sizes, int n_in,
                              void* d_out, int out_size)
{
    const float* x     = (const float*)d_in[0];
    const float* Wqkv0 = (const float*)d_in[1];
    const float* Wqkv1 = (const float*)d_in[2];
    const float* Wproj = (const float*)d_in[3];
    const float* c1w   = (const float*)d_in[4];
    const float* c1b   = (const float*)d_in[5];
    const float* c2w   = (const float*)d_in[6];
    const float* c2b   = (const float*)d_in[7];
    const float* cvl   = (const float*)d_in[8];
    float* out = (float*)d_out;

    cudaFuncSetAttribute(gemm_chain_v5,
                         cudaFuncAttributeMaxDynamicSharedMemorySize, CH_SMEM);

    // #0) qkv GEMMs, both weight sets, scattered epilogue (one launch, z=2)
    gemm_tf32<128, 2, 4, false, 2><<<dim3(12, 16, 2), 256>>>(x, 0, Wqkv0, 0,
        (float*)Wqkv1, 0, 512, 1536, 0, 0, 0, 0, 512, 1.0f);

    // #1) S0 + S1 (one launch, z=32)
    gemm_tf32<128, 2, 4, true, 3><<<dim3(8, 8, 32), 256>>>(nullptr, 0, nullptr, 0,
        nullptr, 0, 64, 64, 1024, 0, 0, 0, 64, 0.125f);

    // #2) softmax S0 AND S1 -> bf16 only (one launch, z=2)
    softmax_rows<2><<<dim3(16384, 1, 2), 256>>>(OFF_S0, 0, OFF_A0H);

    // #3) C_fwd / C_bwd (bf16 mma)  <- ncu capture slot (-s 5 = 4th launch)
    gemm_chain_v5<<<dim3(8, 8, 32), 256, CH_SMEM>>>();

    // #4) fused feat/conv/gates/Smix
    fuse_kernel<<<dim3(32, 32, 16), 256>>>(c1w, c1b, c2w, c2b);

    // #5) A = softmax(Smix) -> S0 buffer (fp32)
    softmax_rows<0><<<16384, 256>>>(OFF_CB, OFF_S0, 0);

    // #6) yb = A @ v0 and ych = Cf @ v1 in ONE launch (z=32)
    gemm_tf32<64, 4, 2, false, 1><<<dim3(1, 8, 32), 256>>>(nullptr, 0, nullptr, 0,
        nullptr, 0, 1024, 64, 64, 0, 0, 0, 1024, 1.0f);

    // #7) combine into Y
    combine_kernel<<<(BH * ND + 255) / 256, 256>>>(cvl);

    // #8) out = Y @ Wproj (tf32 TC)
    gemm_tf32<128, 2, 4, false, 0><<<dim3(4, 16, 1), 256>>>(nullptr, OFF_Y, Wproj, 0, out, 0,
        512, 512, 512, 0, 0, 0, 512, 1.0f);

    (void)in_sizes; (void)n_in; (void)out_size;
}

// round 12
// speedup vs baseline: 1.6676x; 1.4170x over previous
#include <cuda_runtime.h>
#include <cuda_bf16.h>
#include <cstdint>

// ---------------- problem constants ----------------
#define BATCH   2
#define NSEQ    1024
#define DIMF    512
#define HEADS   8
#define DKH     64
#define BH      16              // BATCH*HEADS
#define NN      1048576ull      // NSEQ*NSEQ
#define ND      65536ull        // NSEQ*DKH
#define NN16    16777216ull     // BH*NN

// ---------------- scratch pool (static device memory; allocation-free) -----
#define OFF_Q0  0ull
#define OFF_K0  1048576ull
#define OFF_V0  2097152ull
#define OFF_Q1  3145728ull
#define OFF_K1  4194304ull
#define OFF_V1  5242880ull
#define OFF_S0  6291456ull
#define OFF_S1  (OFF_S0 + NN16)
#define OFF_CF  (OFF_S1 + NN16)
#define OFF_CB  (OFF_CF + NN16)
#define OFF_YB   (OFF_CB + NN16)
#define OFF_YB2  (OFF_YB + 1048576ull)
#define OFF_YCH  (OFF_YB2 + 1048576ull)
#define OFF_YCH2 (OFF_YCH + 1048576ull)
#define OFF_Y    (OFF_YCH2 + 1048576ull)
#define POOL_TOTAL (OFF_Y + 1048576ull)

#define OFF_A0H 0ull
#define OFF_A1H NN16

static __device__ float         g_pool [POOL_TOTAL];
static __device__ __nv_bfloat16 g_poolh[2ull * NN16];

// ---------------- helpers ----------------
__device__ __forceinline__ float tanh_fast(float x) {
    float y;
    asm("tanh.approx.f32 %0, %1;" : "=f"(y) : "f"(x));
    return y;
}

__device__ __forceinline__ uint32_t f2tf32(float x) {
    uint32_t u;
    asm("cvt.rna.tf32.f32 %0, %1;" : "=r"(u) : "f"(x));
    return u;
}

// ---- packed f32x2 (sm_100+) ----
__device__ __forceinline__ uint64_t pk(float lo, float hi) {
    uint64_t r;
    asm("mov.b64 %0, {%1, %2};" : "=l"(r) : "f"(lo), "f"(hi));
    return r;
}
__device__ __forceinline__ void upk(uint64_t v, float& lo, float& hi) {
    asm("mov.b64 {%0, %1}, %2;" : "=f"(lo), "=f"(hi) : "l"(v));
}
__device__ __forceinline__ uint64_t fma2(uint64_t a, uint64_t b, uint64_t c) {
    uint64_t d;
    asm("fma.rn.f32x2 %0, %1, %2, %3;" : "=l"(d) : "l"(a), "l"(b), "l"(c));
    return d;
}
__device__ __forceinline__ uint64_t add2(uint64_t a, uint64_t b) {
    uint64_t d;
    asm("add.rn.f32x2 %0, %1, %2;" : "=l"(d) : "l"(a), "l"(b));
    return d;
}
__device__ __forceinline__ uint64_t mul2(uint64_t a, uint64_t b) {
    uint64_t d;
    asm("mul.rn.f32x2 %0, %1, %2;" : "=l"(d) : "l"(a), "l"(b));
    return d;
}

__device__ __forceinline__ void mma_tf32(float* c, const uint32_t* a, const uint32_t* b) {
    asm volatile(
        "mma.sync.aligned.m16n8k8.row.col.f32.tf32.tf32.f32 "
        "{%0,%1,%2,%3}, {%4,%5,%6,%7}, {%8,%9}, {%0,%1,%2,%3};"
        : "+f"(c[0]), "+f"(c[1]), "+f"(c[2]), "+f"(c[3])
        : "r"(a[0]), "r"(a[1]), "r"(a[2]), "r"(a[3]), "r"(b[0]), "r"(b[1]));
}

__device__ __forceinline__ void mma16816(float* c, const uint32_t* a, const uint32_t* b) {
    asm volatile(
        "mma.sync.aligned.m16n8k16.row.col.f32.bf16.bf16.f32 "
        "{%0,%1,%2,%3}, {%4,%5,%6,%7}, {%8,%9}, {%0,%1,%2,%3};"
        : "+f"(c[0]), "+f"(c[1]), "+f"(c[2]), "+f"(c[3])
        : "r"(a[0]), "r"(a[1]), "r"(a[2]), "r"(a[3]), "r"(b[0]), "r"(b[1]));
}

__device__ __forceinline__ void cp16(void* smem_dst, const void* gmem_src) {
    uint32_t s = (uint32_t)__cvta_generic_to_shared(smem_dst);
    asm volatile("cp.async.cg.shared.global [%0], [%1], 16;\n" :: "r"(s), "l"(gmem_src));
}
__device__ __forceinline__ void cp_commit() {
    asm volatile("cp.async.commit_group;\n");
}
template<int N>
__device__ __forceinline__ void cp_wait() {
    asm volatile("cp.async.wait_group %0;\n" :: "n"(N));
}

__device__ __forceinline__ void ldsm_x4(uint32_t* r, const void* smem) {
    uint32_t a = (uint32_t)__cvta_generic_to_shared(smem);
    asm volatile("ldmatrix.sync.aligned.m8n8.x4.shared.b16 {%0,%1,%2,%3}, [%4];\n"
        : "=r"(r[0]), "=r"(r[1]), "=r"(r[2]), "=r"(r[3]) : "r"(a));
}
__device__ __forceinline__ void ldsm_x4t(uint32_t* r, const void* smem) {
    uint32_t a = (uint32_t)__cvta_generic_to_shared(smem);
    asm volatile("ldmatrix.sync.aligned.m8n8.x4.trans.shared.b16 {%0,%1,%2,%3}, [%4];\n"
        : "=r"(r[0]), "=r"(r[1]), "=r"(r[2]), "=r"(r[3]) : "r"(a));
}

// =====================================================================
// tf32 tensor-core GEMM, batched. MODE:
//  0: generic  C = alpha * A@B(^T), pool offsets / ext pointers
//  1: AV dual + split-K2. z bits: [5]=which(0 yb,1 ych), [4]=K-half, [3:0]=bh
//  2: QKV fused-scatter: A=x, B = (z? Wqkv1 : Wqkv0), epilogue writes
//     directly into q/k/v [BH][N][DK] layouts
//  3: S dual   z<16: S0 = q0 k0^T /8 ; z>=16: S1 = q1 k1^T /8
// =====================================================================
template<int BN, int WARPS_M, int WARPS_N, bool TRANSB, int MODE>
__global__ __launch_bounds__(256) void gemm_tf32(
    const float* __restrict__ Aext, size_t offA,
    const float* __restrict__ Bext, size_t offB,
    float* __restrict__ Cext, size_t offC,
    int lda, int ldb, int ldc,
    long long sA, long long sB, long long sC,
    int K, float alpha)
{
    constexpr int BM = 128, BK = 32, LDS = BK + 4;     // stride 36
    constexpr int WM = BM / WARPS_M;
    constexpr int WN = BN / WARPS_N;
    constexpr int MT = WM / 16;
    constexpr int NT = WN / 8;
    constexpr int BITERS = BN / 32;

    const float* A;
    const float* B;
    float*       C = nullptr;
    int z = blockIdx.z;
    if (MODE == 1) {
        int which = z >> 5;
        int half  = (z >> 4) & 1;
        int zz    = z & 15;
        if (which == 0) {
            A = g_pool + OFF_S0 + (size_t)zz * NN + (size_t)half * 512;
            B = g_pool + OFF_V0 + (size_t)zz * ND + (size_t)half * 512 * 64;
            C = g_pool + (half ? OFF_YB2 : OFF_YB) + (size_t)zz * ND;
        } else {
            A = g_pool + OFF_CF + (size_t)zz * NN + (size_t)half * 512;
            B = g_pool + OFF_V1 + (size_t)zz * ND + (size_t)half * 512 * 64;
            C = g_pool + (half ? OFF_YCH2 : OFF_YCH) + (size_t)zz * ND;
        }
    } else if (MODE == 2) {
        A = Aext;
        B = z ? (const float*)Cext : Bext;   // Wqkv1 smuggled via Cext
    } else if (MODE == 3) {
        int zz = z & 15;
        if (z < 16) {
            A = g_pool + OFF_Q0 + (size_t)zz * ND;
            B = g_pool + OFF_K0 + (size_t)zz * ND;
            C = g_pool + OFF_S0 + (size_t)zz * NN;
        } else {
            A = g_pool + OFF_Q1 + (size_t)zz * ND;
            B = g_pool + OFF_K1 + (size_t)zz * ND;
            C = g_pool + OFF_S1 + (size_t)zz * NN;
        }
    } else {
        A = (Aext ? Aext : (g_pool + offA)) + (size_t)z * (size_t)sA;
        B = (Bext ? Bext : (g_pool + offB)) + (size_t)z * (size_t)sB;
        C = (Cext ? Cext : (g_pool + offC)) + (size_t)z * (size_t)sC;
    }

    __shared__ uint32_t As[BM][LDS];
    __shared__ uint32_t Bs[BN][LDS];   // stored [n][k]

    int tid  = threadIdx.x;
    int warp = tid >> 5, lane = tid & 31;
    int grp  = lane >> 2, kq = lane & 3;
    int bm = blockIdx.y * BM, bn = blockIdx.x * BN;
    int wm = (warp / WARPS_N) * WM, wn = (warp % WARPS_N) * WN;

    float acc[MT][NT][4] = {};

    for (int k0 = 0; k0 < K; k0 += BK) {
        #pragma unroll
        for (int i = 0; i < 4; i++) {
            int linear = i * 256 + tid;
            int r = linear >> 3, c4 = linear & 7;
            float4 v = *(const float4*)&A[(size_t)(bm + r) * lda + k0 + c4 * 4];
            uint4 u = make_uint4(f2tf32(v.x), f2tf32(v.y), f2tf32(v.z), f2tf32(v.w));
            *(uint4*)&As[r][c4 * 4] = u;
        }
        if (TRANSB) {
            #pragma unroll
            for (int i = 0; i < BITERS; i++) {
                int linear = i * 256 + tid;
                int n = linear >> 3, c4 = linear & 7;
                float4 v = *(const float4*)&B[(size_t)(bn + n) * ldb + k0 + c4 * 4];
                uint4 u = make_uint4(f2tf32(v.x), f2tf32(v.y), f2tf32(v.z), f2tf32(v.w));
                *(uint4*)&Bs[n][c4 * 4] = u;
            }
        } else {
            #pragma unroll
            for (int i = 0; i < BITERS; i++) {
                int linear = i * 256 + tid;
                int n4 = linear % (BN / 4), k = linear / (BN / 4);
                float4 v = *(const float4*)&B[(size_t)(k0 + k) * ldb + bn + n4 * 4];
                Bs[n4 * 4 + 0][k] = f2tf32(v.x);
                Bs[n4 * 4 + 1][k] = f2tf32(v.y);
                Bs[n4 * 4 + 2][k] = f2tf32(v.z);
                Bs[n4 * 4 + 3][k] = f2tf32(v.w);
            }
        }
        __syncthreads();

        #pragma unroll
        for (int ks = 0; ks < 4; ks++) {
            int kc = ks * 8 + kq;
            uint32_t a[MT][4], b[NT][2];
            #pragma unroll
            for (int mt = 0; mt < MT; mt++) {
                int r = wm + mt * 16 + grp;
                a[mt][0] = As[r][kc];
                a[mt][1] = As[r + 8][kc];
                a[mt][2] = As[r][kc + 4];
                a[mt][3] = As[r + 8][kc + 4];
            }
            #pragma unroll
            for (int nt = 0; nt < NT; nt++) {
                int n = wn + nt * 8 + grp;
                b[nt][0] = Bs[n][kc];
                b[nt][1] = Bs[n][kc + 4];
            }
            #pragma unroll
            for (int mt = 0; mt < MT; mt++)
                #pragma unroll
                for (int nt = 0; nt < NT; nt++)
                    mma_tf32(acc[mt][nt], a[mt], b[nt]);
        }
        __syncthreads();
    }

    if (MODE == 2) {
        // scatter epilogue: col j -> (s, h, d); row r -> (b, tok)
        size_t qoff = z ? OFF_Q1 : OFF_Q0;
        size_t koff = z ? OFF_K1 : OFF_K0;
        size_t voff = z ? OFF_V1 : OFF_V0;
        #pragma unroll
        for (int mt = 0; mt < MT; mt++) {
            #pragma unroll
            for (int nt = 0; nt < NT; nt++) {
                #pragma unroll
                for (int half = 0; half < 2; half++) {
                    int r  = bm + wm + mt * 16 + grp + half * 8;
                    int cg = bn + wn + nt * 8 + kq * 2;
                    int bb = r >> 10, tok = r & 1023;
                    int s = cg >> 9, h = (cg >> 6) & 7, d = cg & 63;
                    size_t base = (s == 0) ? qoff : (s == 1) ? koff : voff;
                    float2 val = half ? make_float2(acc[mt][nt][2], acc[mt][nt][3])
                                      : make_float2(acc[mt][nt][0], acc[mt][nt][1]);
                    *(float2*)&g_pool[base + ((size_t)(bb * 8 + h) * 1024 + tok) * 64 + d] = val;
                }
            }
        }
        return;
    }

    #pragma unroll
    for (int mt = 0; mt < MT; mt++) {
        #pragma unroll
        for (int nt = 0; nt < NT; nt++) {
            int r = bm + wm + mt * 16 + grp;
            int c = bn + wn + nt * 8 + kq * 2;
            *(float2*)&C[(size_t)r * ldc + c] =
                make_float2(alpha * acc[mt][nt][0], alpha * acc[mt][nt][1]);
            *(float2*)&C[(size_t)(r + 8) * ldc + c] =
                make_float2(alpha * acc[mt][nt][2], alpha * acc[mt][nt][3]);
        }
    }
}

// =====================================================================
// Row softmax over 1024 elems (vectorized).
// WB=0: fp32 out only.  WB=2: bf16 out ONLY (batched over z).
// =====================================================================
template<int WB>
__global__ __launch_bounds__(256) void softmax_rows(size_t inOff, size_t outOff, size_t bfOff)
{
    size_t zoff = (WB == 2) ? (size_t)blockIdx.z * NN16 : 0;
    const float* S = g_pool + inOff + zoff;
    size_t base = (size_t)blockIdx.x * 1024;
    int tid = threadIdx.x;
    int warp = tid >> 5, lane = tid & 31;

    float4 v4 = *(const float4*)&S[base + tid * 4];
    float v[4] = { v4.x, v4.y, v4.z, v4.w };
    float mx = fmaxf(fmaxf(v[0], v[1]), fmaxf(v[2], v[3]));
    #pragma unroll
    for (int o = 16; o > 0; o >>= 1) mx = fmaxf(mx, __shfl_xor_sync(0xffffffffu, mx, o));
    __shared__ float red[8];
    if (lane == 0) red[warp] = mx;
    __syncthreads();
    float mAll = red[0];
    #pragma unroll
    for (int w = 1; w < 8; w++) mAll = fmaxf(mAll, red[w]);
    __syncthreads();

    float e[4], s = 0.f;
    #pragma unroll
    for (int i = 0; i < 4; i++) { e[i] = __expf(v[i] - mAll); s += e[i]; }
    #pragma unroll
    for (int o = 16; o > 0; o >>= 1) s += __shfl_xor_sync(0xffffffffu, s, o);
    if (lane == 0) red[warp] = s;
    __syncthreads();
    float tot = 0.f;
    #pragma unroll
    for (int w = 0; w < 8; w++) tot += red[w];
    float inv = __fdividef(1.0f, tot);

    float p[4];
    #pragma unroll
    for (int i = 0; i < 4; i++) p[i] = e[i] * inv;
    if (WB == 0) {
        float* A = g_pool + outOff;
        *(float4*)&A[base + tid * 4] = make_float4(p[0], p[1], p[2], p[3]);
    } else {
        __nv_bfloat162 lo = __floats2bfloat162_rn(p[0], p[1]);
        __nv_bfloat162 hi = __floats2bfloat162_rn(p[2], p[3]);
        *(uint32_t*)&g_poolh[bfOff + zoff + base + tid * 4] = *(uint32_t*)&lo;
        *(uint32_t*)&g_poolh[bfOff + zoff + base + tid * 4 + 2] = *(uint32_t*)&hi;
    }
}

// =====================================================================
// Chain GEMM v5: bf16 mma.sync, 2-stage cp.async, BK=64, 2 CTAs/SM.
// =====================================================================
#define CH_ASTR 72
#define CH_BSTR 136
#define CH_AELEM (128 * CH_ASTR)            // 9216
#define CH_BELEM (64 * CH_BSTR)             // 8704
#define CH_STAGE (CH_AELEM + CH_BELEM)      // 17920 elems
#define CH_SMEM  (2 * CH_STAGE * 2)         // 71,680 bytes

__global__ __launch_bounds__(256, 2) void gemm_chain_v5() {
    extern __shared__ __nv_bfloat16 sm[];

    int z = blockIdx.z;
    const __nv_bfloat16 *A, *B;
    float* C;
    if (z < 16) {
        A = g_poolh + OFF_A0H + (size_t)z * NN;
        B = g_poolh + OFF_A1H + (size_t)z * NN;
        C = g_pool  + OFF_CF  + (size_t)z * NN;
    } else {
        int zz = z - 16;
        A = g_poolh + OFF_A1H + (size_t)zz * NN;
        B = g_poolh + OFF_A0H + (size_t)zz * NN;
        C = g_pool  + OFF_CB  + (size_t)zz * NN;
    }

    int tid = threadIdx.x, warp = tid >> 5, lane = tid & 31;
    int bm = blockIdx.y * 128, bn = blockIdx.x * 128;
    int wm = (warp >> 2) * 64, wn = (warp & 3) * 32;

    auto load_stage = [&](int chunk, int s) {
        __nv_bfloat16* Ab = sm + s * CH_STAGE;
        __nv_bfloat16* Bb = Ab + CH_AELEM;
        int k0 = chunk * 64;
        #pragma unroll
        for (int i = 0; i < 4; i++) {
            int idx = i * 256 + tid;
            int r = idx >> 3, c16 = idx & 7;
            cp16(Ab + r * CH_ASTR + c16 * 8,
                 A + (size_t)(bm + r) * 1024 + k0 + c16 * 8);
        }
        #pragma unroll
        for (int i = 0; i < 4; i++) {
            int idx = i * 256 + tid;
            int k = idx >> 4, c16 = idx & 15;
            cp16(Bb + k * CH_BSTR + c16 * 8,
                 B + (size_t)(k0 + k) * 1024 + bn + c16 * 8);
        }
    };

    float acc[4][4][4] = {};

    load_stage(0, 0); cp_commit();

    for (int c = 0; c < 16; c++) {
        cp_wait<0>();
        __syncthreads();

        if (c + 1 < 16) { load_stage(c + 1, (c + 1) & 1); cp_commit(); }

        const __nv_bfloat16* Ab = sm + (c & 1) * CH_STAGE;
        const __nv_bfloat16* Bb = Ab + CH_AELEM;

        #pragma unroll
        for (int ks = 0; ks < 4; ks++) {
            int kb = ks * 16;
            uint32_t a[4][4], b[4][2];
            #pragma unroll
            for (int mt = 0; mt < 4; mt++)
                ldsm_x4(a[mt], Ab + (wm + mt * 16 + (lane & 15)) * CH_ASTR
                                  + kb + ((lane >> 4) << 3));
            #pragma unroll
            for (int p = 0; p < 2; p++) {
                uint32_t r[4];
                ldsm_x4t(r, Bb + (kb + (lane & 7) + (((lane >> 3) & 1) << 3)) * CH_BSTR
                               + wn + p * 16 + ((lane >> 4) << 3));
                b[2 * p][0] = r[0]; b[2 * p][1] = r[1];
                b[2 * p + 1][0] = r[2]; b[2 * p + 1][1] = r[3];
            }
            #pragma unroll
            for (int mt = 0; mt < 4; mt++)
                #pragma unroll
                for (int nt = 0; nt < 4; nt++)
                    mma16816(acc[mt][nt], a[mt], b[nt]);
        }
        __syncthreads();
    }

    #pragma unroll
    for (int mt = 0; mt < 4; mt++) {
        #pragma unroll
        for (int nt = 0; nt < 4; nt++) {
            int r = bm + wm + mt * 16 + (lane >> 2);
            int cc = bn + wn + nt * 8 + (lane & 3) * 2;
            *(float2*)&C[(size_t)r * 1024 + cc]       = make_float2(acc[mt][nt][0], acc[mt][nt][1]);
            *(float2*)&C[(size_t)(r + 8) * 1024 + cc] = make_float2(acc[mt][nt][2], acc[mt][nt][3]);
        }
    }
}

// =====================================================================
// Fused v2: feat -> conv1+gelu -> conv2+sigmoid -> gates -> Smix (in Cb).
// Packed f32x2 math; 32x64 tile; 8 elements (4 col-pairs) per thread;
// weights pre-broadcast to float2 in smem.
// grid (16, 32, 16), 256 threads.
// =====================================================================
__global__ __launch_bounds__(256) void fuse_kernel(
    const float* __restrict__ w1, const float* __restrict__ b1,
    const float* __restrict__ w2, const float* __restrict__ b2)
{
    __shared__ float s0t[64][33], s1t[64][33];
    __shared__ float2 w1p[16][6];
    __shared__ float2 b1p[16];
    __shared__ float2 w2p[4][16];
    __shared__ float2 b2p[4];

    size_t off = (size_t)blockIdx.z * NN;
    int m0 = blockIdx.y * 32, n0 = blockIdx.x * 64;
    int tid = threadIdx.x;

    if (tid < 96)       { float v = w1[tid];       w1p[tid / 6][tid % 6]   = make_float2(v, v); }
    else if (tid < 112) { float v = b1[tid - 96];  b1p[tid - 96]           = make_float2(v, v); }
    else if (tid < 176) { int j = tid - 112; float v = w2[j]; w2p[j / 16][j % 16] = make_float2(v, v); }
    else if (tid < 180) { float v = b2[tid - 176]; b2p[tid - 176]          = make_float2(v, v); }

    const float* S0 = g_pool + OFF_S0;
    const float* S1 = g_pool + OFF_S1;
    const float* Cf = g_pool + OFF_CF;
    float*       Cb = g_pool + OFF_CB;

    #pragma unroll
    for (int i = 0; i < 8; i++) {
        int idx = i * 256 + tid;
        int cc = idx >> 5, rr = idx & 31;
        s0t[cc][rr] = S0[off + (size_t)(n0 + cc) * 1024 + m0 + rr];
        s1t[cc][rr] = S1[off + (size_t)(n0 + cc) * 1024 + m0 + rr];
    }
    __syncthreads();

    int txp = tid & 31;   // column pair (cols n0+2txp, n0+2txp+1)
    int tyr = tid >> 5;   // row group (rows tyr, tyr+8, tyr+16, tyr+24)

    uint64_t f[4][6];
    size_t gidx[4];
    #pragma unroll
    for (int r = 0; r < 4; r++) {
        int row = tyr + r * 8;
        size_t gi = off + (size_t)(m0 + row) * 1024 + n0 + txp * 2;
        gidx[r] = gi;
        float2 s0v = *(const float2*)&S0[gi];
        float2 s1v = *(const float2*)&S1[gi];
        float2 cfv = *(const float2*)&Cf[gi];
        float2 cbv = *(const float2*)&Cb[gi];
        f[r][0] = pk(s0v.x, s0v.y);
        f[r][1] = pk(s1v.x, s1v.y);
        f[r][2] = pk(s0t[txp * 2][row], s0t[txp * 2 + 1][row]);
        f[r][3] = pk(s1t[txp * 2][row], s1t[txp * 2 + 1][row]);
        f[r][4] = pk(__logf(cfv.x + 1e-6f), __logf(cfv.y + 1e-6f));
        f[r][5] = pk(__logf(cbv.x + 1e-6f), __logf(cbv.y + 1e-6f));
    }

    const uint64_t ONE2  = pk(1.0f, 1.0f);
    const uint64_t C0447 = pk(0.044715f, 0.044715f);
    const uint64_t CSQ2  = pk(0.7978845608028654f, 0.7978845608028654f);
    const uint64_t HALF2 = pk(0.5f, 0.5f);

    uint64_t g2[4][4];
    #pragma unroll
    for (int r = 0; r < 4; r++)
        #pragma unroll
        for (int o = 0; o < 4; o++)
            g2[r][o] = *(const uint64_t*)&b2p[o];

    #pragma unroll 4
    for (int oh = 0; oh < 16; oh++) {
        uint64_t w1c[6], w2c[4];
        uint64_t b1c = *(const uint64_t*)&b1p[oh];
        #pragma unroll
        for (int c = 0; c < 6; c++) w1c[c] = *(const uint64_t*)&w1p[oh][c];
        #pragma unroll
        for (int o = 0; o < 4; o++) w2c[o] = *(const uint64_t*)&w2p[o][oh];

        #pragma unroll
        for (int r = 0; r < 4; r++) {
            uint64_t a2 = b1c;
            #pragma unroll
            for (int c = 0; c < 6; c++) a2 = fma2(w1c[c], f[r][c], a2);
            uint64_t asq   = mul2(a2, a2);
            uint64_t inner = fma2(C0447, asq, ONE2);
            uint64_t gx    = mul2(CSQ2, mul2(a2, inner));
            float gl, gh;
            upk(gx, gl, gh);
            uint64_t t2 = pk(tanh_fast(gl), tanh_fast(gh));
            uint64_t hg = mul2(mul2(HALF2, a2), add2(t2, ONE2));
            #pragma unroll
            for (int o = 0; o < 4; o++) g2[r][o] = fma2(w2c[o], hg, g2[r][o]);
        }
    }

    #pragma unroll
    for (int r = 0; r < 4; r++) {
        float gL[4], gH[4];
        #pragma unroll
        for (int o = 0; o < 4; o++) {
            float lo, hi; upk(g2[r][o], lo, hi);
            gL[o] = __fdividef(1.0f, 1.0f + __expf(-lo));
            gH[o] = __fdividef(1.0f, 1.0f + __expf(-hi));
        }
        float s0x, s0y, s1x, s1y, crx, cry;
        upk(f[r][0], s0x, s0y);
        upk(f[r][1], s1x, s1y);
        upk(f[r][4], crx, cry);
        float dx   = fabsf(s0x - s1x);
        float lsex = fmaxf(s0x, s1x) + __logf(1.0f + __expf(-dx));
        float smx  = s0x + gL[0] * s1x + gL[1] * (lsex - s0x) - gL[2] * (0.5f * s1x) + gL[3] * crx;
        float dy   = fabsf(s0y - s1y);
        float lsey = fmaxf(s0y, s1y) + __logf(1.0f + __expf(-dy));
        float smy  = s0y + gH[0] * s1y + gH[1] * (lsey - s0y) - gH[2] * (0.5f * s1y) + gH[3] * cry;
        *(float2*)&Cb[gidx[r]] = make_float2(smx, smy);
    }
}

// =====================================================================
// Combine: Y = (yb1+yb2) + sigmoid(cvl) * (ych1+ych2), scattered layout
// =====================================================================
__global__ void combine_kernel(const float* __restrict__ cvl) {
    int idx = blockIdx.x * 256 + threadIdx.x;
    if (idx >= (int)(BH * ND)) return;
    int bh  = idx >> 16;
    int rr  = idx & 65535;
    int tok = rr >> 6;
    int d   = rr & 63;
    int b = bh >> 3, h = bh & 7;
    float sig = __fdividef(1.0f, 1.0f + __expf(-cvl[0]));
    float yb  = g_pool[OFF_YB  + (size_t)idx] + g_pool[OFF_YB2  + (size_t)idx];
    float yc  = g_pool[OFF_YCH + (size_t)idx] + g_pool[OFF_YCH2 + (size_t)idx];
    g_pool[OFF_Y + ((size_t)(b * 1024 + tok)) * 512 + h * 64 + d] = yb + sig * yc;
}

// =====================================================================
// Host launch sequence
// =====================================================================
extern "C" void kernel_launch(void* const* d_in, const int* in_sizes, int n_in,
                              void* d_out, int out_size)
{
    const float* x     = (const float*)d_in[0];
    const float* Wqkv0 = (const float*)d_in[1];
    const float* Wqkv1 = (const float*)d_in[2];
    const float* Wproj = (const float*)d_in[3];
    const float* c1w   = (const float*)d_in[4];
    const float* c1b   = (const float*)d_in[5];
    const float* c2w   = (const float*)d_in[6];
    const float* c2b   = (const float*)d_in[7];
    const float* cvl   = (const float*)d_in[8];
    float* out = (float*)d_out;

    cudaFuncSetAttribute(gemm_chain_v5,
                         cudaFuncAttributeMaxDynamicSharedMemorySize, CH_SMEM);

    // #0) qkv GEMMs, both weight sets, scattered epilogue (one launch, z=2)
    gemm_tf32<128, 2, 4, false, 2><<<dim3(12, 16, 2), 256>>>(x, 0, Wqkv0, 0,
        (float*)Wqkv1, 0, 512, 1536, 0, 0, 0, 0, 512, 1.0f);

    // #1) S0 + S1 (one launch, z=32)
    gemm_tf32<128, 2, 4, true, 3><<<dim3(8, 8, 32), 256>>>(nullptr, 0, nullptr, 0,
        nullptr, 0, 64, 64, 1024, 0, 0, 0, 64, 0.125f);

    // #2) softmax S0 AND S1 -> bf16 only (one launch, z=2)
    softmax_rows<2><<<dim3(16384, 1, 2), 256>>>(OFF_S0, 0, OFF_A0H);

    // #3) C_fwd / C_bwd (bf16 mma)  <- ncu capture slot
    gemm_chain_v5<<<dim3(8, 8, 32), 256, CH_SMEM>>>();

    // #4) fused feat/conv/gates/Smix (packed f32x2)
    fuse_kernel<<<dim3(16, 32, 16), 256>>>(c1w, c1b, c2w, c2b);

    // #5) A = softmax(Smix) -> S0 buffer (fp32)
    softmax_rows<0><<<16384, 256>>>(OFF_CB, OFF_S0, 0);

    // #6) yb = A @ v0 and ych = Cf @ v1, split-K2 (one launch, z=64)
    gemm_tf32<64, 4, 2, false, 1><<<dim3(1, 8, 64), 256>>>(nullptr, 0, nullptr, 0,
        nullptr, 0, 1024, 64, 64, 0, 0, 0, 512, 1.0f);

    // #7) combine into Y
    combine_kernel<<<(BH * ND + 255) / 256, 256>>>(cvl);

    // #8) out = Y @ Wproj (tf32 TC)
    gemm_tf32<128, 2, 4, false, 0><<<dim3(4, 16, 1), 256>>>(nullptr, OFF_Y, Wproj, 0, out, 0,
        512, 512, 512, 0, 0, 0, 512, 1.0f);

    (void)in_sizes; (void)n_in; (void)out_size;
}

// round 13
// speedup vs baseline: 1.9306x; 1.1577x over previous
#include <cuda_runtime.h>
#include <cuda_bf16.h>
#include <cstdint>

// ---------------- problem constants ----------------
#define BATCH   2
#define NSEQ    1024
#define DIMF    512
#define HEADS   8
#define DKH     64
#define BH      16              // BATCH*HEADS
#define NN      1048576ull      // NSEQ*NSEQ
#define ND      65536ull        // NSEQ*DKH
#define NN16    16777216ull     // BH*NN

// ---------------- scratch pool (static device memory; allocation-free) -----
#define OFF_Q0  0ull
#define OFF_K0  1048576ull
#define OFF_V0  2097152ull
#define OFF_Q1  3145728ull
#define OFF_K1  4194304ull
#define OFF_V1  5242880ull
#define OFF_S0  6291456ull
#define OFF_S1  (OFF_S0 + NN16)
#define OFF_CF  (OFF_S1 + NN16)
#define OFF_CB  (OFF_CF + NN16)
#define OFF_YB   (OFF_CB + NN16)
#define OFF_YB2  (OFF_YB + 1048576ull)
#define OFF_YCH  (OFF_YB2 + 1048576ull)
#define OFF_YCH2 (OFF_YCH + 1048576ull)
#define OFF_Y    (OFF_YCH2 + 1048576ull)
#define POOL_TOTAL (OFF_Y + 1048576ull)

#define OFF_A0H 0ull
#define OFF_A1H NN16

static __device__ float         g_pool [POOL_TOTAL];
static __device__ __nv_bfloat16 g_poolh[2ull * NN16];

// ---------------- helpers ----------------
__device__ __forceinline__ float tanh_fast(float x) {
    float y;
    asm("tanh.approx.f32 %0, %1;" : "=f"(y) : "f"(x));
    return y;
}

__device__ __forceinline__ uint32_t f2tf32(float x) {
    uint32_t u;
    asm("cvt.rna.tf32.f32 %0, %1;" : "=r"(u) : "f"(x));
    return u;
}

// ---- packed f32x2 (sm_100+) ----
__device__ __forceinline__ uint64_t pk(float lo, float hi) {
    uint64_t r;
    asm("mov.b64 %0, {%1, %2};" : "=l"(r) : "f"(lo), "f"(hi));
    return r;
}
__device__ __forceinline__ void upk(uint64_t v, float& lo, float& hi) {
    asm("mov.b64 {%0, %1}, %2;" : "=f"(lo), "=f"(hi) : "l"(v));
}
__device__ __forceinline__ uint64_t fma2(uint64_t a, uint64_t b, uint64_t c) {
    uint64_t d;
    asm("fma.rn.f32x2 %0, %1, %2, %3;" : "=l"(d) : "l"(a), "l"(b), "l"(c));
    return d;
}
__device__ __forceinline__ uint64_t add2(uint64_t a, uint64_t b) {
    uint64_t d;
    asm("add.rn.f32x2 %0, %1, %2;" : "=l"(d) : "l"(a), "l"(b));
    return d;
}
__device__ __forceinline__ uint64_t mul2(uint64_t a, uint64_t b) {
    uint64_t d;
    asm("mul.rn.f32x2 %0, %1, %2;" : "=l"(d) : "l"(a), "l"(b));
    return d;
}

__device__ __forceinline__ void mma_tf32(float* c, const uint32_t* a, const uint32_t* b) {
    asm volatile(
        "mma.sync.aligned.m16n8k8.row.col.f32.tf32.tf32.f32 "
        "{%0,%1,%2,%3}, {%4,%5,%6,%7}, {%8,%9}, {%0,%1,%2,%3};"
        : "+f"(c[0]), "+f"(c[1]), "+f"(c[2]), "+f"(c[3])
        : "r"(a[0]), "r"(a[1]), "r"(a[2]), "r"(a[3]), "r"(b[0]), "r"(b[1]));
}

__device__ __forceinline__ void mma16816(float* c, const uint32_t* a, const uint32_t* b) {
    asm volatile(
        "mma.sync.aligned.m16n8k16.row.col.f32.bf16.bf16.f32 "
        "{%0,%1,%2,%3}, {%4,%5,%6,%7}, {%8,%9}, {%0,%1,%2,%3};"
        : "+f"(c[0]), "+f"(c[1]), "+f"(c[2]), "+f"(c[3])
        : "r"(a[0]), "r"(a[1]), "r"(a[2]), "r"(a[3]), "r"(b[0]), "r"(b[1]));
}

__device__ __forceinline__ void cp16(void* smem_dst, const void* gmem_src) {
    uint32_t s = (uint32_t)__cvta_generic_to_shared(smem_dst);
    asm volatile("cp.async.cg.shared.global [%0], [%1], 16;\n" :: "r"(s), "l"(gmem_src));
}
__device__ __forceinline__ void cp_commit() {
    asm volatile("cp.async.commit_group;\n");
}
template<int N>
__device__ __forceinline__ void cp_wait() {
    asm volatile("cp.async.wait_group %0;\n" :: "n"(N));
}

__device__ __forceinline__ void ldsm_x4(uint32_t* r, const void* smem) {
    uint32_t a = (uint32_t)__cvta_generic_to_shared(smem);
    asm volatile("ldmatrix.sync.aligned.m8n8.x4.shared.b16 {%0,%1,%2,%3}, [%4];\n"
        : "=r"(r[0]), "=r"(r[1]), "=r"(r[2]), "=r"(r[3]) : "r"(a));
}
__device__ __forceinline__ void ldsm_x4t(uint32_t* r, const void* smem) {
    uint32_t a = (uint32_t)__cvta_generic_to_shared(smem);
    asm volatile("ldmatrix.sync.aligned.m8n8.x4.trans.shared.b16 {%0,%1,%2,%3}, [%4];\n"
        : "=r"(r[0]), "=r"(r[1]), "=r"(r[2]), "=r"(r[3]) : "r"(a));
}

// =====================================================================
// tf32 tensor-core GEMM v2: cp.async double-buffered raw-fp32 tiles,
// cvt.rna at fragment load. Batched. MODE:
//  0: generic  C = alpha * A@B(^T), pool offsets / ext pointers
//  1: AV dual + split-K2. z bits: [5]=which(0 yb,1 ych), [4]=K-half, [3:0]=bh
//  2: QKV fused-scatter: A=x, B = (z? Wqkv1 : Wqkv0), epilogue writes
//     directly into q/k/v [BH][N][DK] layouts
//  3: S dual   z<16: S0 = q0 k0^T /8 ; z>=16: S1 = q1 k1^T /8
// smem: A [2][128][36] raw fp32; B TRANSB [2][BN][36] else [2][32][BN+4].
// =====================================================================
#define TF_AST 36
#define TF_ASTAGE (128 * TF_AST)
#define TF_SMEM(BN_, TRB_) \
    (2 * (TF_ASTAGE + ((TRB_) ? (BN_) * TF_AST : 32 * ((BN_) + 4))) * 4)

template<int BN, int WARPS_M, int WARPS_N, bool TRANSB, int MODE>
__global__ __launch_bounds__(256) void gemm_tf32(
    const float* __restrict__ Aext, size_t offA,
    const float* __restrict__ Bext, size_t offB,
    float* __restrict__ Cext, size_t offC,
    int lda, int ldb, int ldc,
    long long sA, long long sB, long long sC,
    int K, float alpha)
{
    constexpr int BM = 128, BK = 32;
    constexpr int WM = BM / WARPS_M;
    constexpr int WN = BN / WARPS_N;
    constexpr int MT = WM / 16;
    constexpr int NT = WN / 8;
    constexpr int BCOLS  = TRANSB ? (BK + 4) : (BN + 4);
    constexpr int BSTAGE = TRANSB ? (BN * TF_AST) : (BK * BCOLS);

    const float* A;
    const float* B;
    float*       C = nullptr;
    int z = blockIdx.z;
    if (MODE == 1) {
        int which = z >> 5;
        int half  = (z >> 4) & 1;
        int zz    = z & 15;
        if (which == 0) {
            A = g_pool + OFF_S0 + (size_t)zz * NN + (size_t)half * 512;
            B = g_pool + OFF_V0 + (size_t)zz * ND + (size_t)half * 512 * 64;
            C = g_pool + (half ? OFF_YB2 : OFF_YB) + (size_t)zz * ND;
        } else {
            A = g_pool + OFF_CF + (size_t)zz * NN + (size_t)half * 512;
            B = g_pool + OFF_V1 + (size_t)zz * ND + (size_t)half * 512 * 64;
            C = g_pool + (half ? OFF_YCH2 : OFF_YCH) + (size_t)zz * ND;
        }
    } else if (MODE == 2) {
        A = Aext;
        B = z ? (const float*)Cext : Bext;   // Wqkv1 smuggled via Cext
    } else if (MODE == 3) {
        int zz = z & 15;
        if (z < 16) {
            A = g_pool + OFF_Q0 + (size_t)zz * ND;
            B = g_pool + OFF_K0 + (size_t)zz * ND;
            C = g_pool + OFF_S0 + (size_t)zz * NN;
        } else {
            A = g_pool + OFF_Q1 + (size_t)zz * ND;
            B = g_pool + OFF_K1 + (size_t)zz * ND;
            C = g_pool + OFF_S1 + (size_t)zz * NN;
        }
    } else {
        A = (Aext ? Aext : (g_pool + offA)) + (size_t)z * (size_t)sA;
        B = (Bext ? Bext : (g_pool + offB)) + (size_t)z * (size_t)sB;
        C = (Cext ? Cext : (g_pool + offC)) + (size_t)z * (size_t)sC;
    }

    extern __shared__ float smf[];
    float* Abase = smf;                    // [2][TF_ASTAGE]
    float* Bbase = smf + 2 * TF_ASTAGE;    // [2][BSTAGE]

    int tid  = threadIdx.x;
    int warp = tid >> 5, lane = tid & 31;
    int grp  = lane >> 2, kq = lane & 3;
    int bm = blockIdx.y * BM, bn = blockIdx.x * BN;
    int wm = (warp / WARPS_N) * WM, wn = (warp % WARPS_N) * WN;

    auto load_stage = [&](int k0, int s) {
        float* Ab = Abase + s * TF_ASTAGE;
        float* Bb = Bbase + s * BSTAGE;
        // A tile: BM x BK floats, 16B chunks, [m][k] layout
        #pragma unroll
        for (int i = 0; i < (BM * BK / 4) / 256; i++) {
            int idx = i * 256 + tid;
            int r = idx >> 3, c = idx & 7;
            cp16(Ab + r * TF_AST + c * 4, &A[(size_t)(bm + r) * lda + k0 + c * 4]);
        }
        if (TRANSB) {
            // B global [N][K] -> smem [n][k]
            #pragma unroll
            for (int i = 0; i < (BN * BK / 4) / 256; i++) {
                int idx = i * 256 + tid;
                int n = idx >> 3, c = idx & 7;
                cp16(Bb + n * TF_AST + c * 4, &B[(size_t)(bn + n) * ldb + k0 + c * 4]);
            }
        } else {
            // B global [K][N] -> smem [k][n] (native)
            #pragma unroll
            for (int i = 0; i < (BK * BN / 4) / 256; i++) {
                int idx = i * 256 + tid;
                int r = idx / (BN / 4), c = idx % (BN / 4);
                cp16(Bb + r * BCOLS + c * 4, &B[(size_t)(k0 + r) * ldb + bn + c * 4]);
            }
        }
    };

    float acc[MT][NT][4] = {};

    int nchunks = K / BK;
    load_stage(0, 0); cp_commit();

    for (int c = 0; c < nchunks; c++) {
        cp_wait<0>();
        __syncthreads();

        if (c + 1 < nchunks) { load_stage((c + 1) * BK, (c + 1) & 1); cp_commit(); }

        const float* Ab = Abase + (c & 1) * TF_ASTAGE;
        const float* Bb = Bbase + (c & 1) * BSTAGE;

        #pragma unroll
        for (int ks = 0; ks < 4; ks++) {
            int kc = ks * 8 + kq;
            uint32_t a[MT][4], b[NT][2];
            #pragma unroll
            for (int mt = 0; mt < MT; mt++) {
                int r = wm + mt * 16 + grp;
                a[mt][0] = f2tf32(Ab[r * TF_AST + kc]);
                a[mt][1] = f2tf32(Ab[(r + 8) * TF_AST + kc]);
                a[mt][2] = f2tf32(Ab[r * TF_AST + kc + 4]);
                a[mt][3] = f2tf32(Ab[(r + 8) * TF_AST + kc + 4]);
            }
            #pragma unroll
            for (int nt = 0; nt < NT; nt++) {
                int n = wn + nt * 8 + grp;
                if (TRANSB) {
                    b[nt][0] = f2tf32(Bb[n * TF_AST + kc]);
                    b[nt][1] = f2tf32(Bb[n * TF_AST + kc + 4]);
                } else {
                    b[nt][0] = f2tf32(Bb[kc * BCOLS + n]);
                    b[nt][1] = f2tf32(Bb[(kc + 4) * BCOLS + n]);
                }
            }
            #pragma unroll
            for (int mt = 0; mt < MT; mt++)
                #pragma unroll
                for (int nt = 0; nt < NT; nt++)
                    mma_tf32(acc[mt][nt], a[mt], b[nt]);
        }
        __syncthreads();
    }

    if (MODE == 2) {
        // scatter epilogue: col j -> (s, h, d); row r -> (b, tok)
        size_t qoff = z ? OFF_Q1 : OFF_Q0;
        size_t koff = z ? OFF_K1 : OFF_K0;
        size_t voff = z ? OFF_V1 : OFF_V0;
        #pragma unroll
        for (int mt = 0; mt < MT; mt++) {
            #pragma unroll
            for (int nt = 0; nt < NT; nt++) {
                #pragma unroll
                for (int half = 0; half < 2; half++) {
                    int r  = bm + wm + mt * 16 + grp + half * 8;
                    int cg = bn + wn + nt * 8 + kq * 2;
                    int bb = r >> 10, tok = r & 1023;
                    int s = cg >> 9, h = (cg >> 6) & 7, d = cg & 63;
                    size_t base = (s == 0) ? qoff : (s == 1) ? koff : voff;
                    float2 val = half ? make_float2(acc[mt][nt][2], acc[mt][nt][3])
                                      : make_float2(acc[mt][nt][0], acc[mt][nt][1]);
                    *(float2*)&g_pool[base + ((size_t)(bb * 8 + h) * 1024 + tok) * 64 + d] = val;
                }
            }
        }
        return;
    }

    #pragma unroll
    for (int mt = 0; mt < MT; mt++) {
        #pragma unroll
        for (int nt = 0; nt < NT; nt++) {
            int r = bm + wm + mt * 16 + grp;
            int c = bn + wn + nt * 8 + kq * 2;
            *(float2*)&C[(size_t)r * ldc + c] =
                make_float2(alpha * acc[mt][nt][0], alpha * acc[mt][nt][1]);
            *(float2*)&C[(size_t)(r + 8) * ldc + c] =
                make_float2(alpha * acc[mt][nt][2], alpha * acc[mt][nt][3]);
        }
    }
}

// =====================================================================
// Row softmax over 1024 elems (vectorized).
// WB=0: fp32 out only.  WB=2: bf16 out ONLY (batched over z).
// =====================================================================
template<int WB>
__global__ __launch_bounds__(256) void softmax_rows(size_t inOff, size_t outOff, size_t bfOff)
{
    size_t zoff = (WB == 2) ? (size_t)blockIdx.z * NN16 : 0;
    const float* S = g_pool + inOff + zoff;
    size_t base = (size_t)blockIdx.x * 1024;
    int tid = threadIdx.x;
    int warp = tid >> 5, lane = tid & 31;

    float4 v4 = *(const float4*)&S[base + tid * 4];
    float v[4] = { v4.x, v4.y, v4.z, v4.w };
    float mx = fmaxf(fmaxf(v[0], v[1]), fmaxf(v[2], v[3]));
    #pragma unroll
    for (int o = 16; o > 0; o >>= 1) mx = fmaxf(mx, __shfl_xor_sync(0xffffffffu, mx, o));
    __shared__ float red[8];
    if (lane == 0) red[warp] = mx;
    __syncthreads();
    float mAll = red[0];
    #pragma unroll
    for (int w = 1; w < 8; w++) mAll = fmaxf(mAll, red[w]);
    __syncthreads();

    float e[4], s = 0.f;
    #pragma unroll
    for (int i = 0; i < 4; i++) { e[i] = __expf(v[i] - mAll); s += e[i]; }
    #pragma unroll
    for (int o = 16; o > 0; o >>= 1) s += __shfl_xor_sync(0xffffffffu, s, o);
    if (lane == 0) red[warp] = s;
    __syncthreads();
    float tot = 0.f;
    #pragma unroll
    for (int w = 0; w < 8; w++) tot += red[w];
    float inv = __fdividef(1.0f, tot);

    float p[4];
    #pragma unroll
    for (int i = 0; i < 4; i++) p[i] = e[i] * inv;
    if (WB == 0) {
        float* A = g_pool + outOff;
        *(float4*)&A[base + tid * 4] = make_float4(p[0], p[1], p[2], p[3]);
    } else {
        __nv_bfloat162 lo = __floats2bfloat162_rn(p[0], p[1]);
        __nv_bfloat162 hi = __floats2bfloat162_rn(p[2], p[3]);
        *(uint32_t*)&g_poolh[bfOff + zoff + base + tid * 4] = *(uint32_t*)&lo;
        *(uint32_t*)&g_poolh[bfOff + zoff + base + tid * 4 + 2] = *(uint32_t*)&hi;
    }
}

// =====================================================================
// Chain GEMM v5: bf16 mma.sync, 2-stage cp.async, BK=64, 2 CTAs/SM.
// =====================================================================
#define CH_ASTR 72
#define CH_BSTR 136
#define CH_AELEM (128 * CH_ASTR)            // 9216
#define CH_BELEM (64 * CH_BSTR)             // 8704
#define CH_STAGE (CH_AELEM + CH_BELEM)      // 17920 elems
#define CH_SMEM  (2 * CH_STAGE * 2)         // 71,680 bytes

__global__ __launch_bounds__(256, 2) void gemm_chain_v5() {
    extern __shared__ __nv_bfloat16 sm[];

    int z = blockIdx.z;
    const __nv_bfloat16 *A, *B;
    float* C;
    if (z < 16) {
        A = g_poolh + OFF_A0H + (size_t)z * NN;
        B = g_poolh + OFF_A1H + (size_t)z * NN;
        C = g_pool  + OFF_CF  + (size_t)z * NN;
    } else {
        int zz = z - 16;
        A = g_poolh + OFF_A1H + (size_t)zz * NN;
        B = g_poolh + OFF_A0H + (size_t)zz * NN;
        C = g_pool  + OFF_CB  + (size_t)zz * NN;
    }

    int tid = threadIdx.x, warp = tid >> 5, lane = tid & 31;
    int bm = blockIdx.y * 128, bn = blockIdx.x * 128;
    int wm = (warp >> 2) * 64, wn = (warp & 3) * 32;

    auto load_stage = [&](int chunk, int s) {
        __nv_bfloat16* Ab = sm + s * CH_STAGE;
        __nv_bfloat16* Bb = Ab + CH_AELEM;
        int k0 = chunk * 64;
        #pragma unroll
        for (int i = 0; i < 4; i++) {
            int idx = i * 256 + tid;
            int r = idx >> 3, c16 = idx & 7;
            cp16(Ab + r * CH_ASTR + c16 * 8,
                 A + (size_t)(bm + r) * 1024 + k0 + c16 * 8);
        }
        #pragma unroll
        for (int i = 0; i < 4; i++) {
            int idx = i * 256 + tid;
            int k = idx >> 4, c16 = idx & 15;
            cp16(Bb + k * CH_BSTR + c16 * 8,
                 B + (size_t)(k0 + k) * 1024 + bn + c16 * 8);
        }
    };

    float acc[4][4][4] = {};

    load_stage(0, 0); cp_commit();

    for (int c = 0; c < 16; c++) {
        cp_wait<0>();
        __syncthreads();

        if (c + 1 < 16) { load_stage(c + 1, (c + 1) & 1); cp_commit(); }

        const __nv_bfloat16* Ab = sm + (c & 1) * CH_STAGE;
        const __nv_bfloat16* Bb = Ab + CH_AELEM;

        #pragma unroll
        for (int ks = 0; ks < 4; ks++) {
            int kb = ks * 16;
            uint32_t a[4][4], b[4][2];
            #pragma unroll
            for (int mt = 0; mt < 4; mt++)
                ldsm_x4(a[mt], Ab + (wm + mt * 16 + (lane & 15)) * CH_ASTR
                                  + kb + ((lane >> 4) << 3));
            #pragma unroll
            for (int p = 0; p < 2; p++) {
                uint32_t r[4];
                ldsm_x4t(r, Bb + (kb + (lane & 7) + (((lane >> 3) & 1) << 3)) * CH_BSTR
                               + wn + p * 16 + ((lane >> 4) << 3));
                b[2 * p][0] = r[0]; b[2 * p][1] = r[1];
                b[2 * p + 1][0] = r[2]; b[2 * p + 1][1] = r[3];
            }
            #pragma unroll
            for (int mt = 0; mt < 4; mt++)
                #pragma unroll
                for (int nt = 0; nt < 4; nt++)
                    mma16816(acc[mt][nt], a[mt], b[nt]);
        }
        __syncthreads();
    }

    #pragma unroll
    for (int mt = 0; mt < 4; mt++) {
        #pragma unroll
        for (int nt = 0; nt < 4; nt++) {
            int r = bm + wm + mt * 16 + (lane >> 2);
            int cc = bn + wn + nt * 8 + (lane & 3) * 2;
            *(float2*)&C[(size_t)r * 1024 + cc]       = make_float2(acc[mt][nt][0], acc[mt][nt][1]);
            *(float2*)&C[(size_t)(r + 8) * 1024 + cc] = make_float2(acc[mt][nt][2], acc[mt][nt][3]);
        }
    }
}

// =====================================================================
// Fused v2: feat -> conv1+gelu -> conv2+sigmoid -> gates -> Smix (in Cb).
// Packed f32x2 math; 32x64 tile; weights pre-broadcast to float2 in smem.
// grid (16, 32, 16), 256 threads.
// =====================================================================
__global__ __launch_bounds__(256) void fuse_kernel(
    const float* __restrict__ w1, const float* __restrict__ b1,
    const float* __restrict__ w2, const float* __restrict__ b2)
{
    __shared__ float s0t[64][33], s1t[64][33];
    __shared__ float2 w1p[16][6];
    __shared__ float2 b1p[16];
    __shared__ float2 w2p[4][16];
    __shared__ float2 b2p[4];

    size_t off = (size_t)blockIdx.z * NN;
    int m0 = blockIdx.y * 32, n0 = blockIdx.x * 64;
    int tid = threadIdx.x;

    if (tid < 96)       { float v = w1[tid];       w1p[tid / 6][tid % 6]   = make_float2(v, v); }
    else if (tid < 112) { float v = b1[tid - 96];  b1p[tid - 96]           = make_float2(v, v); }
    else if (tid < 176) { int j = tid - 112; float v = w2[j]; w2p[j / 16][j % 16] = make_float2(v, v); }
    else if (tid < 180) { float v = b2[tid - 176]; b2p[tid - 176]          = make_float2(v, v); }

    const float* S0 = g_pool + OFF_S0;
    const float* S1 = g_pool + OFF_S1;
    const float* Cf = g_pool + OFF_CF;
    float*       Cb = g_pool + OFF_CB;

    #pragma unroll
    for (int i = 0; i < 8; i++) {
        int idx = i * 256 + tid;
        int cc = idx >> 5, rr = idx & 31;
        s0t[cc][rr] = S0[off + (size_t)(n0 + cc) * 1024 + m0 + rr];
        s1t[cc][rr] = S1[off + (size_t)(n0 + cc) * 1024 + m0 + rr];
    }
    __syncthreads();

    int txp = tid & 31;   // column pair (cols n0+2txp, n0+2txp+1)
    int tyr = tid >> 5;   // row group (rows tyr, tyr+8, tyr+16, tyr+24)

    uint64_t f[4][6];
    size_t gidx[4];
    #pragma unroll
    for (int r = 0; r < 4; r++) {
        int row = tyr + r * 8;
        size_t gi = off + (size_t)(m0 + row) * 1024 + n0 + txp * 2;
        gidx[r] = gi;
        float2 s0v = *(const float2*)&S0[gi];
        float2 s1v = *(const float2*)&S1[gi];
        float2 cfv = *(const float2*)&Cf[gi];
        float2 cbv = *(const float2*)&Cb[gi];
        f[r][0] = pk(s0v.x, s0v.y);
        f[r][1] = pk(s1v.x, s1v.y);
        f[r][2] = pk(s0t[txp * 2][row], s0t[txp * 2 + 1][row]);
        f[r][3] = pk(s1t[txp * 2][row], s1t[txp * 2 + 1][row]);
        f[r][4] = pk(__logf(cfv.x + 1e-6f), __logf(cfv.y + 1e-6f));
        f[r][5] = pk(__logf(cbv.x + 1e-6f), __logf(cbv.y + 1e-6f));
    }

    const uint64_t ONE2  = pk(1.0f, 1.0f);
    const uint64_t C0447 = pk(0.044715f, 0.044715f);
    const uint64_t CSQ2  = pk(0.7978845608028654f, 0.7978845608028654f);
    const uint64_t HALF2 = pk(0.5f, 0.5f);

    uint64_t g2[4][4];
    #pragma unroll
    for (int r = 0; r < 4; r++)
        #pragma unroll
        for (int o = 0; o < 4; o++)
            g2[r][o] = *(const uint64_t*)&b2p[o];

    #pragma unroll 4
    for (int oh = 0; oh < 16; oh++) {
        uint64_t w1c[6], w2c[4];
        uint64_t b1c = *(const uint64_t*)&b1p[oh];
        #pragma unroll
        for (int c = 0; c < 6; c++) w1c[c] = *(const uint64_t*)&w1p[oh][c];
        #pragma unroll
        for (int o = 0; o < 4; o++) w2c[o] = *(const uint64_t*)&w2p[o][oh];

        #pragma unroll
        for (int r = 0; r < 4; r++) {
            uint64_t a2 = b1c;
            #pragma unroll
            for (int c = 0; c < 6; c++) a2 = fma2(w1c[c], f[r][c], a2);
            uint64_t asq   = mul2(a2, a2);
            uint64_t inner = fma2(C0447, asq, ONE2);
            uint64_t gx    = mul2(CSQ2, mul2(a2, inner));
            float gl, gh;
            upk(gx, gl, gh);
            uint64_t t2 = pk(tanh_fast(gl), tanh_fast(gh));
            uint64_t hg = mul2(mul2(HALF2, a2), add2(t2, ONE2));
            #pragma unroll
            for (int o = 0; o < 4; o++) g2[r][o] = fma2(w2c[o], hg, g2[r][o]);
        }
    }

    #pragma unroll
    for (int r = 0; r < 4; r++) {
        float gL[4], gH[4];
        #pragma unroll
        for (int o = 0; o < 4; o++) {
            float lo, hi; upk(g2[r][o], lo, hi);
            gL[o] = __fdividef(1.0f, 1.0f + __expf(-lo));
            gH[o] = __fdividef(1.0f, 1.0f + __expf(-hi));
        }
        float s0x, s0y, s1x, s1y, crx, cry;
        upk(f[r][0], s0x, s0y);
        upk(f[r][1], s1x, s1y);
        upk(f[r][4], crx, cry);
        float dx   = fabsf(s0x - s1x);
        float lsex = fmaxf(s0x, s1x) + __logf(1.0f + __expf(-dx));
        float smx  = s0x + gL[0] * s1x + gL[1] * (lsex - s0x) - gL[2] * (0.5f * s1x) + gL[3] * crx;
        float dy   = fabsf(s0y - s1y);
        float lsey = fmaxf(s0y, s1y) + __logf(1.0f + __expf(-dy));
        float smy  = s0y + gH[0] * s1y + gH[1] * (lsey - s0y) - gH[2] * (0.5f * s1y) + gH[3] * cry;
        *(float2*)&Cb[gidx[r]] = make_float2(smx, smy);
    }
}

// =====================================================================
// Combine: Y = (yb1+yb2) + sigmoid(cvl) * (ych1+ych2), scattered layout
// =====================================================================
__global__ void combine_kernel(const float* __restrict__ cvl) {
    int idx = blockIdx.x * 256 + threadIdx.x;
    if (idx >= (int)(BH * ND)) return;
    int bh  = idx >> 16;
    int rr  = idx & 65535;
    int tok = rr >> 6;
    int d   = rr & 63;
    int b = bh >> 3, h = bh & 7;
    float sig = __fdividef(1.0f, 1.0f + __expf(-cvl[0]));
    float yb  = g_pool[OFF_YB  + (size_t)idx] + g_pool[OFF_YB2  + (size_t)idx];
    float yc  = g_pool[OFF_YCH + (size_t)idx] + g_pool[OFF_YCH2 + (size_t)idx];
    g_pool[OFF_Y + ((size_t)(b * 1024 + tok)) * 512 + h * 64 + d] = yb + sig * yc;
}

// =====================================================================
// Host launch sequence
// =====================================================================
extern "C" void kernel_launch(void* const* d_in, const int* in_sizes, int n_in,
                              void* d_out, int out_size)
{
    const float* x     = (const float*)d_in[0];
    const float* Wqkv0 = (const float*)d_in[1];
    const float* Wqkv1 = (const float*)d_in[2];
    const float* Wproj = (const float*)d_in[3];
    const float* c1w   = (const float*)d_in[4];
    const float* c1b   = (const float*)d_in[5];
    const float* c2w   = (const float*)d_in[6];
    const float* c2b   = (const float*)d_in[7];
    const float* cvl   = (const float*)d_in[8];
    float* out = (float*)d_out;

    cudaFuncSetAttribute(gemm_chain_v5,
                         cudaFuncAttributeMaxDynamicSharedMemorySize, CH_SMEM);
    cudaFuncSetAttribute(gemm_tf32<128, 2, 4, false, 2>,
                         cudaFuncAttributeMaxDynamicSharedMemorySize, TF_SMEM(128, false));
    cudaFuncSetAttribute(gemm_tf32<128, 2, 4, true, 3>,
                         cudaFuncAttributeMaxDynamicSharedMemorySize, TF_SMEM(128, true));
    cudaFuncSetAttribute(gemm_tf32<64, 4, 2, false, 1>,
                         cudaFuncAttributeMaxDynamicSharedMemorySize, TF_SMEM(64, false));
    cudaFuncSetAttribute(gemm_tf32<128, 2, 4, false, 0>,
                         cudaFuncAttributeMaxDynamicSharedMemorySize, TF_SMEM(128, false));

    // #0) qkv GEMMs, both weight sets, scattered epilogue (one launch, z=2)
    gemm_tf32<128, 2, 4, false, 2><<<dim3(12, 16, 2), 256, TF_SMEM(128, false)>>>(
        x, 0, Wqkv0, 0, (float*)Wqkv1, 0, 512, 1536, 0, 0, 0, 0, 512, 1.0f);

    // #1) S0 + S1 (one launch, z=32)
    gemm_tf32<128, 2, 4, true, 3><<<dim3(8, 8, 32), 256, TF_SMEM(128, true)>>>(
        nullptr, 0, nullptr, 0, nullptr, 0, 64, 64, 1024, 0, 0, 0, 64, 0.125f);

    // #2) softmax S0 AND S1 -> bf16 only (one launch, z=2)
    softmax_rows<2><<<dim3(16384, 1, 2), 256>>>(OFF_S0, 0, OFF_A0H);

    // #3) C_fwd / C_bwd (bf16 mma)  <- ncu capture slot
    gemm_chain_v5<<<dim3(8, 8, 32), 256, CH_SMEM>>>();

    // #4) fused feat/conv/gates/Smix (packed f32x2)
    fuse_kernel<<<dim3(16, 32, 16), 256>>>(c1w, c1b, c2w, c2b);

    // #5) A = softmax(Smix) -> S0 buffer (fp32)
    softmax_rows<0><<<16384, 256>>>(OFF_CB, OFF_S0, 0);

    // #6) yb = A @ v0 and ych = Cf @ v1, split-K2 (one launch, z=64)
    gemm_tf32<64, 4, 2, false, 1><<<dim3(1, 8, 64), 256, TF_SMEM(64, false)>>>(
        nullptr, 0, nullptr, 0, nullptr, 0, 1024, 64, 64, 0, 0, 0, 512, 1.0f);

    // #7) combine into Y
    combine_kernel<<<(BH * ND + 255) / 256, 256>>>(cvl);

    // #8) out = Y @ Wproj (tf32 TC)
    gemm_tf32<128, 2, 4, false, 0><<<dim3(4, 16, 1), 256, TF_SMEM(128, false)>>>(
        nullptr, OFF_Y, Wproj, 0, out, 0, 512, 512, 512, 0, 0, 0, 512, 1.0f);

    (void)in_sizes; (void)n_in; (void)out_size;
}